// round 2
// baseline (speedup 1.0000x reference)
#include <cuda_runtime.h>
#include <math.h>

#define B  64
#define S  64
#define E  256
#define H  512
#define H2 1024
#define H4 2048
#define DH 1024
#define T  30
#define J4 512

// ---------------- device scratch (static globals; no allocations) ----------------
__device__ float g_xg0[2*2*B*S*H4];   // [inp][dir][B*S][4H] layer0 input projections
__device__ float g_xg1[2*2*B*S*H4];   // layer1 input projections
__device__ float g_y0[2*B*S*H2];      // [inp][B*S][2H] layer0 bi-output
__device__ float g_y1[2*B*S*H2];      // layer1 bi-output (encoder output)
__device__ float g_h[2*4*B*H];        // double-buffered h for 4 sequences
__device__ float g_c[4*B*H];          // c for 4 sequences
__device__ float g_dh0[2*B*DH];       // decoder layer0 h (double buffered)
__device__ float g_dc0[B*DH];
__device__ float g_dh1[2*B*DH];
__device__ float g_dc1[B*DH];
__device__ float g_ctx[B*DH];         // constant context = sum_s enc_a
__device__ float g_curctx[B*DH];      // current "context part" of decoder input
__device__ float g_curkey[B*J4];      // current "keyframe part" of decoder input

__device__ __forceinline__ float sigf(float x) { return 1.f / (1.f + __expf(-x)); }

// ---------------- generic fp32 GEMM: C[M,N] = A[M,K] @ W[N,K]^T + bias[N] ----------------
// 128x128 block, BK=8, 256 threads, 8x8 per thread.
__global__ void sgemm_bias(const float* __restrict__ A, const float* __restrict__ W,
                           const float* __restrict__ bias, float* __restrict__ C,
                           int M, int N, int K)
{
    __shared__ float As[8][128];
    __shared__ float Ws[8][128];
    const int tid = threadIdx.x;
    const int tx = tid & 15, ty = tid >> 4;
    const float* Ab = A + (size_t)blockIdx.y * 128 * K;
    const float* Wb = W + (size_t)blockIdx.x * 128 * K;

    float acc[8][8];
#pragma unroll
    for (int i = 0; i < 8; i++)
#pragma unroll
        for (int j = 0; j < 8; j++) acc[i][j] = 0.f;

    const int lrow = tid >> 1;         // 0..127
    const int lk   = (tid & 1) * 4;    // 0 or 4

    for (int k0 = 0; k0 < K; k0 += 8) {
        float4 av = *(const float4*)(Ab + (size_t)lrow * K + k0 + lk);
        float4 wv = *(const float4*)(Wb + (size_t)lrow * K + k0 + lk);
        As[lk + 0][lrow] = av.x; As[lk + 1][lrow] = av.y;
        As[lk + 2][lrow] = av.z; As[lk + 3][lrow] = av.w;
        Ws[lk + 0][lrow] = wv.x; Ws[lk + 1][lrow] = wv.y;
        Ws[lk + 2][lrow] = wv.z; Ws[lk + 3][lrow] = wv.w;
        __syncthreads();
#pragma unroll
        for (int k = 0; k < 8; k++) {
            float4 a0 = *(const float4*)(&As[k][ty * 8 + 0]);
            float4 a1 = *(const float4*)(&As[k][ty * 8 + 4]);
            float4 w0 = *(const float4*)(&Ws[k][tx * 8 + 0]);
            float4 w1 = *(const float4*)(&Ws[k][tx * 8 + 4]);
            float a[8] = {a0.x,a0.y,a0.z,a0.w,a1.x,a1.y,a1.z,a1.w};
            float w[8] = {w0.x,w0.y,w0.z,w0.w,w1.x,w1.y,w1.z,w1.w};
#pragma unroll
            for (int i = 0; i < 8; i++)
#pragma unroll
                for (int j = 0; j < 8; j++) acc[i][j] += a[i] * w[j];
        }
        __syncthreads();
    }

    const int m0 = blockIdx.y * 128 + ty * 8;
    const int n0 = blockIdx.x * 128 + tx * 8;
#pragma unroll
    for (int i = 0; i < 8; i++) {
        float* Cr = C + (size_t)(m0 + i) * N + n0;
#pragma unroll
        for (int j = 0; j < 8; j++) Cr[j] = acc[i][j] + bias[n0 + j];
    }
}

// ---------------- zero LSTM states ----------------
__global__ void zero_states()
{
    int i = blockIdx.x * blockDim.x + threadIdx.x;
    if (i < 2 * 4 * B * H) g_h[i] = 0.f;
    if (i < 4 * B * H)     g_c[i] = 0.f;
}

// ---------------- encoder recurrence step (both layers share this) ----------------
// grid = 128 blocks: 4 sequences (inp x dir) x 32 tiles of 16 hidden units.
// Each block computes gates for 64 batches x 16 units x 4 gates (K = H = 512),
// then applies the LSTM cell and writes h/c/y. One launch per time step.
__global__ void enc_step(const float* __restrict__ xg,   // [4][B*S][4H]
                         const float* __restrict__ Whh,  // [2][4H][H]
                         float* __restrict__ y,          // [2][B*S][2H]
                         int t)
{
    const int blk  = blockIdx.x;
    const int seq  = blk >> 5;          // 0..3
    const int tile = blk & 31;          // 0..31
    const int inp  = seq >> 1, dir = seq & 1;
    const int j0   = tile * 16;
    const int pos  = dir ? (S - 1 - t) : t;

    const float* hprev = g_h + (size_t)(t & 1) * 4 * B * H + (size_t)seq * B * H;
    float* hnext       = g_h + (size_t)((t + 1) & 1) * 4 * B * H + (size_t)seq * B * H;
    float* cbuf        = g_c + (size_t)seq * B * H;
    const float* Wd    = Whh + (size_t)dir * H4 * H;
    const float* xgb   = xg + (size_t)(inp * 2 + dir) * B * S * H4;

    const int tid = threadIdx.x;
    const int tx = tid & 15;   // unit within tile
    const int ty = tid >> 4;   // 0..15, 4 batches each

    __shared__ float sA[16][65];   // [kk][b]
    __shared__ float sW[16][65];   // [kk][q*16+u]

    float acc[4][4];
#pragma unroll
    for (int a = 0; a < 4; a++)
#pragma unroll
        for (int b = 0; b < 4; b++) acc[a][b] = 0.f;

    const int lb = tid >> 4;   // 0..15
    const int lk = tid & 15;

    for (int k0 = 0; k0 < H; k0 += 16) {
#pragma unroll
        for (int r = 0; r < 4; r++)
            sA[lk][r * 16 + lb] = hprev[(size_t)(r * 16 + lb) * H + k0 + lk];
#pragma unroll
        for (int r = 0; r < 4; r++) {
            int col = r * 16 + lb;
            int q = col >> 4, u = col & 15;
            sW[lk][col] = Wd[(size_t)(q * H + j0 + u) * H + k0 + lk];
        }
        __syncthreads();
#pragma unroll
        for (int kk = 0; kk < 16; kk++) {
            float w0 = sW[kk][tx], w1 = sW[kk][16 + tx];
            float w2 = sW[kk][32 + tx], w3 = sW[kk][48 + tx];
#pragma unroll
            for (int bb = 0; bb < 4; bb++) {
                float a = sA[kk][ty * 4 + bb];
                acc[bb][0] += a * w0; acc[bb][1] += a * w1;
                acc[bb][2] += a * w2; acc[bb][3] += a * w3;
            }
        }
        __syncthreads();
    }

    const int j = j0 + tx;
#pragma unroll
    for (int bb = 0; bb < 4; bb++) {
        int b = ty * 4 + bb;
        const float* xr = xgb + (size_t)(b * S + pos) * H4;
        float gi = acc[bb][0] + xr[0 * H + j];
        float gf = acc[bb][1] + xr[1 * H + j];
        float gg = acc[bb][2] + xr[2 * H + j];
        float go = acc[bb][3] + xr[3 * H + j];
        float iv = sigf(gi), fv = sigf(gf), gv = tanhf(gg), ov = sigf(go);
        float c  = cbuf[(size_t)b * H + j];
        float cn = fv * c + iv * gv;
        float hn = ov * tanhf(cn);
        cbuf[(size_t)b * H + j]  = cn;
        hnext[(size_t)b * H + j] = hn;
        y[(size_t)(inp * B * S + b * S + pos) * H2 + dir * H + j] = hn;
    }
}

// ---------------- decoder setup ----------------
__global__ void dec_setup()
{
    int idx = blockIdx.x * blockDim.x + threadIdx.x;   // over B*DH
    if (idx >= B * DH) return;
    int b = idx / DH, u = idx % DH;

    // context = sum_s enc_a  (degenerate softmax -> ones)
    float s = 0.f;
    for (int t = 0; t < S; t++) s += g_y1[(size_t)(b * S + t) * H2 + u];
    g_ctx[idx] = s;

    // x0 = [enc_a[:, -1], enc_b[:, 0, :H]]
    g_curctx[idx] = g_y1[(size_t)(b * S + S - 1) * H2 + u];
    if (u < J4) g_curkey[b * J4 + u] = g_y1[(size_t)(B * S + b * S + 0) * H2 + u];

    // decoder init states: concat of last-layer backward-dir final (h,c) of a and b
    // seq = inp*2 + dir ; after 64 steps the final h is in buffer (64 & 1) == 0
    float hv, cv;
    if (u < H) { hv = g_h[(size_t)1 * B * H + (size_t)b * H + u];
                 cv = g_c[(size_t)1 * B * H + (size_t)b * H + u]; }
    else       { hv = g_h[(size_t)3 * B * H + (size_t)b * H + (u - H)];
                 cv = g_c[(size_t)3 * B * H + (size_t)b * H + (u - H)]; }
    g_dh0[idx] = hv; g_dc0[idx] = cv;
    g_dh1[idx] = hv; g_dc1[idx] = cv;
}

// ---------------- decoder layer step (shared by layer0/layer1 via segments) ----------------
// grid = 128 blocks: 2 batch tiles (32) x 64 unit tiles (16). 256 threads.
// Each thread: 2 batches x 1 unit x 4 gates.
__device__ __forceinline__ void dec_gemm_cell(
    const float* Aps[3], const int ldAs[3],
    const float* Wps[3], const int ldws[3], const int koffs[3], const int Kls[3],
    int nseg, const float* bias, float* cbuf, float* hnext)
{
    const int blk = blockIdx.x;
    const int btile = blk >> 6;
    const int j0 = (blk & 63) * 16;
    const int tid = threadIdx.x;
    const int tx = tid & 15, ty = tid >> 4;

    __shared__ float sA[16][33];
    __shared__ float sW[16][65];

    float acc[2][4];
#pragma unroll
    for (int a = 0; a < 2; a++)
#pragma unroll
        for (int q = 0; q < 4; q++) acc[a][q] = 0.f;

    const int lb = tid >> 4, lk = tid & 15;

    for (int s3 = 0; s3 < nseg; s3++) {
        const float* Ap = Aps[s3]; int ldA = ldAs[s3];
        const float* Wp = Wps[s3]; int ldw = ldws[s3];
        int koff = koffs[s3], Kl = Kls[s3];
        for (int k0 = 0; k0 < Kl; k0 += 16) {
#pragma unroll
            for (int r = 0; r < 2; r++)
                sA[lk][r * 16 + lb] = Ap[(size_t)(btile * 32 + r * 16 + lb) * ldA + k0 + lk];
#pragma unroll
            for (int r = 0; r < 4; r++) {
                int col = r * 16 + lb;
                int q = col >> 4, u = col & 15;
                sW[lk][col] = Wp[(size_t)(q * DH + j0 + u) * ldw + koff + k0 + lk];
            }
            __syncthreads();
#pragma unroll
            for (int kk = 0; kk < 16; kk++) {
                float w0 = sW[kk][tx], w1 = sW[kk][16 + tx];
                float w2 = sW[kk][32 + tx], w3 = sW[kk][48 + tx];
#pragma unroll
                for (int bb = 0; bb < 2; bb++) {
                    float a = sA[kk][ty * 2 + bb];
                    acc[bb][0] += a * w0; acc[bb][1] += a * w1;
                    acc[bb][2] += a * w2; acc[bb][3] += a * w3;
                }
            }
            __syncthreads();
        }
    }

    const int j = j0 + tx;
#pragma unroll
    for (int bb = 0; bb < 2; bb++) {
        int b = btile * 32 + ty * 2 + bb;
        float gi = acc[bb][0] + bias[0 * DH + j];
        float gf = acc[bb][1] + bias[1 * DH + j];
        float gg = acc[bb][2] + bias[2 * DH + j];
        float go = acc[bb][3] + bias[3 * DH + j];
        float iv = sigf(gi), fv = sigf(gf), gv = tanhf(gg), ov = sigf(go);
        float c = cbuf[(size_t)b * DH + j];
        float cn = fv * c + iv * gv;
        float hn = ov * tanhf(cn);
        cbuf[(size_t)b * DH + j]  = cn;
        hnext[(size_t)b * DH + j] = hn;
    }
}

__global__ void dec_step0(const float* __restrict__ Wih, const float* __restrict__ Whh,
                          const float* __restrict__ bias, int t)
{
    const float* h0 = g_dh0 + (size_t)(t & 1) * B * DH;
    float* h0n      = g_dh0 + (size_t)((t + 1) & 1) * B * DH;
    const float* Aps[3]  = { g_curctx, g_curkey, h0 };
    const int    ldAs[3] = { DH, J4, DH };
    const float* Wps[3]  = { Wih, Wih, Whh };
    const int    ldws[3] = { 1536, 1536, 1024 };
    const int    koffs[3]= { 0, 1024, 0 };
    const int    Kls[3]  = { 1024, 512, 1024 };
    dec_gemm_cell(Aps, ldAs, Wps, ldws, koffs, Kls, 3, bias, g_dc0, h0n);
}

__global__ void dec_step1(const float* __restrict__ Wih, const float* __restrict__ Whh,
                          const float* __restrict__ bias, int t)
{
    const float* h0n = g_dh0 + (size_t)((t + 1) & 1) * B * DH;
    const float* h1  = g_dh1 + (size_t)(t & 1) * B * DH;
    float* h1n       = g_dh1 + (size_t)((t + 1) & 1) * B * DH;
    const float* Aps[3]  = { h0n, h1, h1 };
    const int    ldAs[3] = { DH, DH, DH };
    const float* Wps[3]  = { Wih, Whh, Whh };
    const int    ldws[3] = { 1024, 1024, 1024 };
    const int    koffs[3]= { 0, 0, 0 };
    const int    Kls[3]  = { 1024, 1024, 0 };
    dec_gemm_cell(Aps, ldAs, Wps, ldws, koffs, Kls, 2, bias, g_dc1, h1n);
}

// ---------------- decoder output projection + next-input assembly ----------------
// grid = 32 blocks x 256 threads; block handles 16 output cols for all 64 batches.
__global__ void dec_out(const float* __restrict__ outW, const float* __restrict__ outb,
                        float* __restrict__ out, int t)
{
    const float* h1n = g_dh1 + (size_t)((t + 1) & 1) * B * DH;
    const int n0 = blockIdx.x * 16;
    const int tid = threadIdx.x;
    const int tx = tid & 15, ty = tid >> 4;

    __shared__ float sA[16][65];
    __shared__ float sW[16][17];

    float acc[4] = {0.f, 0.f, 0.f, 0.f};
    const int lb = tid >> 4, lk = tid & 15;

    for (int k0 = 0; k0 < DH; k0 += 16) {
#pragma unroll
        for (int r = 0; r < 4; r++)
            sA[lk][r * 16 + lb] = h1n[(size_t)(r * 16 + lb) * DH + k0 + lk];
        sW[lk][lb] = outW[(size_t)(n0 + lb) * DH + k0 + lk];
        __syncthreads();
#pragma unroll
        for (int kk = 0; kk < 16; kk++) {
            float w = sW[kk][tx];
#pragma unroll
            for (int bb = 0; bb < 4; bb++) acc[bb] += sA[kk][ty * 4 + bb] * w;
        }
        __syncthreads();
    }

    const int n = n0 + tx;
#pragma unroll
    for (int bb = 0; bb < 4; bb++) {
        int b = ty * 4 + bb;
        float v = acc[bb] + outb[n];
        out[(size_t)(b * T + t) * J4 + n] = v;
        g_curkey[b * J4 + n] = v;
    }
    // refresh the context part of the decoder input (constant after step 0)
    for (int i = 0; i < 8; i++) {
        int idx = i * 256 + tid;            // 2048 entries: 64 b x 32 cols
        int b = idx >> 5;
        int u = (idx & 31) + blockIdx.x * 32;
        g_curctx[b * DH + u] = g_ctx[b * DH + u];
    }
}

// ---------------- launch ----------------
extern "C" void kernel_launch(void* const* d_in, const int* in_sizes, int n_in,
                              void* d_out, int out_size)
{
    const float* sa     = (const float*)d_in[0];
    const float* sb     = (const float*)d_in[1];
    const float* eWih0  = (const float*)d_in[2];
    const float* eWhh0  = (const float*)d_in[3];
    const float* eb0    = (const float*)d_in[4];
    const float* eWih1  = (const float*)d_in[5];
    const float* eWhh1  = (const float*)d_in[6];
    const float* eb1    = (const float*)d_in[7];
    const float* dWih0  = (const float*)d_in[8];
    const float* dWhh0  = (const float*)d_in[9];
    const float* db0    = (const float*)d_in[10];
    const float* dWih1  = (const float*)d_in[11];
    const float* dWhh1  = (const float*)d_in[12];
    const float* db1    = (const float*)d_in[13];
    const float* outW   = (const float*)d_in[16];
    const float* outb   = (const float*)d_in[17];
    float* out = (float*)d_out;

    float *p_xg0, *p_xg1, *p_y0, *p_y1;
    cudaGetSymbolAddress((void**)&p_xg0, g_xg0);
    cudaGetSymbolAddress((void**)&p_xg1, g_xg1);
    cudaGetSymbolAddress((void**)&p_y0,  g_y0);
    cudaGetSymbolAddress((void**)&p_y1,  g_y1);

    dim3 gemm_grid(H4 / 128, (B * S) / 128);   // (16, 32)

    // layer-0 input projections: x @ Wih0^T + b0 for both inputs, both dirs
    for (int inp = 0; inp < 2; inp++)
        for (int dir = 0; dir < 2; dir++)
            sgemm_bias<<<gemm_grid, 256>>>(
                inp ? sb : sa,
                eWih0 + (size_t)dir * H4 * E,
                eb0 + (size_t)dir * H4,
                p_xg0 + (size_t)(inp * 2 + dir) * B * S * H4,
                B * S, H4, E);

    zero_states<<<(2 * 4 * B * H + 255) / 256, 256>>>();
    for (int t = 0; t < S; t++)
        enc_step<<<128, 256>>>(p_xg0, eWhh0, p_y0, t);

    // layer-1 input projections: y0 @ Wih1^T + b1
    for (int inp = 0; inp < 2; inp++)
        for (int dir = 0; dir < 2; dir++)
            sgemm_bias<<<gemm_grid, 256>>>(
                p_y0 + (size_t)inp * B * S * H2,
                eWih1 + (size_t)dir * H4 * H2,
                eb1 + (size_t)dir * H4,
                p_xg1 + (size_t)(inp * 2 + dir) * B * S * H4,
                B * S, H4, H2);

    zero_states<<<(2 * 4 * B * H + 255) / 256, 256>>>();
    for (int t = 0; t < S; t++)
        enc_step<<<128, 256>>>(p_xg1, eWhh1, p_y1, t);

    dec_setup<<<(B * DH + 255) / 256, 256>>>();

    for (int t = 0; t < T; t++) {
        dec_step0<<<128, 256>>>(dWih0, dWhh0, db0, t);
        dec_step1<<<128, 256>>>(dWih1, dWhh1, db1, t);
        dec_out<<<32, 256>>>(outW, outb, out, t);
    }
}

// round 3
// speedup vs baseline: 1.6936x; 1.6936x over previous
#include <cuda_runtime.h>
#include <math.h>

#define B  64
#define S  64
#define E  256
#define H  512
#define H2 1024
#define H4 2048
#define DH 1024
#define T  30
#define J4 512
#define ENC_NB 128
#define DEC_NB 128

// ---------------- device scratch ----------------
__device__ float g_xg0[4*B*S*H4];
__device__ float g_xg1[4*B*S*H4];
__device__ float g_y0[2*B*S*H2];
__device__ float g_y1[2*B*S*H2];
__device__ float g_h[2*4*B*H];     // [buf][seq][b][H]
__device__ float g_c[4*B*H];       // final c per seq (written at last step of layer1)
__device__ float g_dh0[2*B*DH];
__device__ float g_dh1[2*B*DH];
__device__ float g_ctx[B*DH];
__device__ float g_curctx[B*DH];
__device__ float g_curkey[B*J4];
__device__ unsigned g_bar;

__device__ __forceinline__ float sigf(float x){ return 1.f/(1.f+__expf(-x)); }

__device__ __forceinline__ void grid_bar(unsigned nb, unsigned &tgt){
    __syncthreads();
    if (threadIdx.x == 0){
        __threadfence();
        tgt += nb;
        atomicAdd(&g_bar, 1u);
        while (*((volatile unsigned*)&g_bar) < tgt) __nanosleep(64);
        __threadfence();
    }
    __syncthreads();
}

__global__ void reset_bar(){ g_bar = 0u; }

// ---------------- fp32 GEMM: C[M,N] = A[M,K] @ W[N,K]^T + bias[N] ----------------
__global__ void sgemm_bias(const float* __restrict__ A, const float* __restrict__ W,
                           const float* __restrict__ bias, float* __restrict__ C,
                           int M, int N, int K)
{
    __shared__ float As[8][128];
    __shared__ float Ws[8][128];
    const int tid = threadIdx.x;
    const int tx = tid & 15, ty = tid >> 4;
    const float* Ab = A + (size_t)blockIdx.y * 128 * K;
    const float* Wb = W + (size_t)blockIdx.x * 128 * K;

    float acc[8][8];
#pragma unroll
    for (int i = 0; i < 8; i++)
#pragma unroll
        for (int j = 0; j < 8; j++) acc[i][j] = 0.f;

    const int lrow = tid >> 1;
    const int lk   = (tid & 1) * 4;

    for (int k0 = 0; k0 < K; k0 += 8) {
        float4 av = *(const float4*)(Ab + (size_t)lrow * K + k0 + lk);
        float4 wv = *(const float4*)(Wb + (size_t)lrow * K + k0 + lk);
        As[lk + 0][lrow] = av.x; As[lk + 1][lrow] = av.y;
        As[lk + 2][lrow] = av.z; As[lk + 3][lrow] = av.w;
        Ws[lk + 0][lrow] = wv.x; Ws[lk + 1][lrow] = wv.y;
        Ws[lk + 2][lrow] = wv.z; Ws[lk + 3][lrow] = wv.w;
        __syncthreads();
#pragma unroll
        for (int k = 0; k < 8; k++) {
            float4 a0 = *(const float4*)(&As[k][ty * 8 + 0]);
            float4 a1 = *(const float4*)(&As[k][ty * 8 + 4]);
            float4 w0 = *(const float4*)(&Ws[k][tx * 8 + 0]);
            float4 w1 = *(const float4*)(&Ws[k][tx * 8 + 4]);
            float a[8] = {a0.x,a0.y,a0.z,a0.w,a1.x,a1.y,a1.z,a1.w};
            float w[8] = {w0.x,w0.y,w0.z,w0.w,w1.x,w1.y,w1.z,w1.w};
#pragma unroll
            for (int i = 0; i < 8; i++)
#pragma unroll
                for (int j = 0; j < 8; j++) acc[i][j] += a[i] * w[j];
        }
        __syncthreads();
    }

    const int m0 = blockIdx.y * 128 + ty * 8;
    const int n0 = blockIdx.x * 128 + tx * 8;
#pragma unroll
    for (int i = 0; i < 8; i++) {
        float* Cr = C + (size_t)(m0 + i) * N + n0;
#pragma unroll
        for (int j = 0; j < 8; j++) Cr[j] = acc[i][j] + bias[n0 + j];
    }
}

// ---------------- persistent encoder layer ----------------
// grid 128 = 4 seq x 32 unit-tiles (16 units). Whh slice SMEM-stationary (k-major,
// cols interleaved unit-major: c = u*4 + q). c state in registers. 64 steps internal.
#define SA_LD 72
#define ENC_SMEM ((512*64 + 2*16*SA_LD) * 4)

__global__ void __launch_bounds__(256, 1) enc_persist(
    const float* __restrict__ xg, const float* __restrict__ Whh,
    float* __restrict__ y, int write_final_c)
{
    extern __shared__ float sm[];
    float* sW = sm;                 // [512][64]
    float* sA = sm + 512*64;        // [2][16][SA_LD]

    const int blk = blockIdx.x;
    const int seq = blk >> 5, tile = blk & 31;
    const int inp = seq >> 1, dir = seq & 1;
    const int j0 = tile * 16;
    const int tid = threadIdx.x;
    const int tu = tid & 15;        // unit
    const int tb = tid >> 4;        // batch group of 4
    unsigned tgt = 0;

    const float* Wd  = Whh + (size_t)dir * H4 * H;
    const float* xgb = xg + (size_t)seq * B * S * H4;

    // one-time: load W slice into SMEM, k-major
    {
        int c = tid & 63;
        int kbase = (tid >> 6) * 128;
        int q = c & 3, u = c >> 2;
        const float* src = Wd + (size_t)(q * H + j0 + u) * H + kbase;
        for (int i = 0; i < 128; i += 4) {
            float4 v = __ldg((const float4*)(src + i));
            sW[(kbase+i+0)*64 + c] = v.x;
            sW[(kbase+i+1)*64 + c] = v.y;
            sW[(kbase+i+2)*64 + c] = v.z;
            sW[(kbase+i+3)*64 + c] = v.w;
        }
    }
    // zero our slice of h buffer 0
    {
        int u = tid & 15, b0 = (tid >> 4) * 4;
        for (int i = 0; i < 4; i++)
            g_h[(size_t)seq*B*H + (size_t)(b0+i)*H + j0 + u] = 0.f;
    }
    float creg[4] = {0.f,0.f,0.f,0.f};
    grid_bar(ENC_NB, tgt);

    const int aB = tid & 63;          // staging: batch
    const int aK = (tid >> 6) * 4;    // staging: k offset in chunk

    for (int t = 0; t < S; t++) {
        const int pos = dir ? (S-1-t) : t;
        const float* hprev = g_h + (size_t)(t&1)*4*B*H + (size_t)seq*B*H;
        float* hnext       = g_h + (size_t)((t+1)&1)*4*B*H + (size_t)seq*B*H;

        // prefetch xg for the cell update (used ~30us later)
        float xgv[4][4];
#pragma unroll
        for (int bb = 0; bb < 4; bb++) {
            const float* xr = xgb + (size_t)((tb*4+bb)*S + pos)*H4 + j0 + tu;
#pragma unroll
            for (int q = 0; q < 4; q++) xgv[bb][q] = __ldg(xr + q*H);
        }

        float acc[4][4];
#pragma unroll
        for (int i = 0; i < 4; i++)
#pragma unroll
            for (int j = 0; j < 4; j++) acc[i][j] = 0.f;

        // GEMM: acc[b][q] = sum_k h[b][k] * W[c=u*4+q][k]
        int buf = 0;
        float4 pa = __ldcg((const float4*)(hprev + (size_t)aB*H + aK));
        {   // store chunk 0 (previous step's readers were fenced by grid_bar)
            float* d = sA + (size_t)(buf*16 + aK)*SA_LD + aB;
            d[0] = pa.x; d[SA_LD] = pa.y; d[2*SA_LD] = pa.z; d[3*SA_LD] = pa.w;
        }
        for (int ch = 0; ch < 32; ch++) {
            __syncthreads();
            if (ch < 31)
                pa = __ldcg((const float4*)(hprev + (size_t)aB*H + (ch+1)*16 + aK));
#pragma unroll
            for (int kk = 0; kk < 16; kk++) {
                float4 av = *(const float4*)(sA + (size_t)(buf*16+kk)*SA_LD + tb*4);
                float4 wv = *(const float4*)(sW + (size_t)(ch*16+kk)*64 + tu*4);
                acc[0][0] += av.x*wv.x; acc[0][1] += av.x*wv.y; acc[0][2] += av.x*wv.z; acc[0][3] += av.x*wv.w;
                acc[1][0] += av.y*wv.x; acc[1][1] += av.y*wv.y; acc[1][2] += av.y*wv.z; acc[1][3] += av.y*wv.w;
                acc[2][0] += av.z*wv.x; acc[2][1] += av.z*wv.y; acc[2][2] += av.z*wv.z; acc[2][3] += av.z*wv.w;
                acc[3][0] += av.w*wv.x; acc[3][1] += av.w*wv.y; acc[3][2] += av.w*wv.z; acc[3][3] += av.w*wv.w;
            }
            if (ch < 31) {
                buf ^= 1;
                float* d = sA + (size_t)(buf*16 + aK)*SA_LD + aB;
                d[0] = pa.x; d[SA_LD] = pa.y; d[2*SA_LD] = pa.z; d[3*SA_LD] = pa.w;
            }
        }

        // cell + writes
        const int j = j0 + tu;
#pragma unroll
        for (int bb = 0; bb < 4; bb++) {
            int b = tb*4 + bb;
            float iv = sigf(acc[bb][0] + xgv[bb][0]);
            float fv = sigf(acc[bb][1] + xgv[bb][1]);
            float gv = tanhf(acc[bb][2] + xgv[bb][2]);
            float ov = sigf(acc[bb][3] + xgv[bb][3]);
            float cn = fv * creg[bb] + iv * gv;
            float hn = ov * tanhf(cn);
            creg[bb] = cn;
            hnext[(size_t)b*H + j] = hn;
            y[(size_t)(inp*B*S + b*S + pos)*H2 + dir*H + j] = hn;
        }
        grid_bar(ENC_NB, tgt);
    }

    if (write_final_c) {
#pragma unroll
        for (int bb = 0; bb < 4; bb++)
            g_c[(size_t)seq*B*H + (size_t)(tb*4+bb)*H + j0 + tu] = creg[bb];
    }
}

// ---------------- decoder setup ----------------
__global__ void dec_setup()
{
    if (blockIdx.x == 0 && threadIdx.x == 0) g_bar = 0u;
    int idx = blockIdx.x * blockDim.x + threadIdx.x;   // over B*DH
    if (idx >= B * DH) return;
    int b = idx / DH, u = idx % DH;

    float s = 0.f;
    for (int t = 0; t < S; t++) s += g_y1[(size_t)(b * S + t) * H2 + u];
    g_ctx[idx] = s;

    g_curctx[idx] = g_y1[(size_t)(b * S + S - 1) * H2 + u];
    if (u < J4) g_curkey[b * J4 + u] = g_y1[(size_t)(B * S + b * S + 0) * H2 + u];

    float hv;
    if (u < H) hv = g_h[(size_t)1 * B * H + (size_t)b * H + u];
    else       hv = g_h[(size_t)3 * B * H + (size_t)b * H + (u - H)];
    g_dh0[idx] = hv;
    g_dh1[idx] = hv;
}

// ---------------- persistent decoder ----------------
// grid 128 x 256. Block owns 8 units (32 gate cols, unit-major interleave) of both
// decoder layers + 4 output cols. c0/c1 in registers. 30 steps, 3 barriers each.
__global__ void __launch_bounds__(256, 1) dec_persist(
    const float* __restrict__ Wih0, const float* __restrict__ Whh0, const float* __restrict__ b0,
    const float* __restrict__ Wih1, const float* __restrict__ Whh1, const float* __restrict__ b1,
    const float* __restrict__ outW, const float* __restrict__ outb,
    float* __restrict__ out)
{
    __shared__ float sA[2*16*SA_LD];
    __shared__ float sW[2*16*32];
    __shared__ float sWc[2*16*4];

    const int blk = blockIdx.x;
    const int j0 = blk * 8;            // first unit of this block (0..1023)
    const int tid = threadIdx.x;
    const int tu = tid & 7;            // unit in tile
    const int tb = tid >> 3;           // 0..31, 2 batches each
    unsigned tgt = 0;

    const int aB = tid & 63, aK = (tid >> 6) * 4;      // a staging
    const int wC = tid & 31, wK = (tid >> 5) * 2;      // w staging (32 cols x 16 k, float2)
    const int wq = wC & 3, wu = wC >> 2;

    // register cell state
    float c0reg[2], c1reg[2];
#pragma unroll
    for (int bb = 0; bb < 2; bb++) {
        int b = tb*2 + bb;
        int u = j0 + tu;
        float cv = (u < H) ? g_c[(size_t)1*B*H + (size_t)b*H + u]
                           : g_c[(size_t)3*B*H + (size_t)b*H + (u - H)];
        c0reg[bb] = cv; c1reg[bb] = cv;
    }
    // biases
    float bia0[4], bia1[4];
    {
        int j = j0 + tu;
#pragma unroll
        for (int q = 0; q < 4; q++) { bia0[q] = __ldg(b0 + q*DH + j); bia1[q] = __ldg(b1 + q*DH + j); }
    }

    for (int t = 0; t < T; t++) {
        const float* h0prev = g_dh0 + (size_t)(t&1)*B*DH;
        float* h0n          = g_dh0 + (size_t)((t+1)&1)*B*DH;
        const float* h1prev = g_dh1 + (size_t)(t&1)*B*DH;
        float* h1n          = g_dh1 + (size_t)((t+1)&1)*B*DH;

        // ---------- phase A: layer-0 gates + cell ----------
        {
            const float* Aps[3]  = { g_curctx, g_curkey, h0prev };
            const int    lAs[3]  = { DH, J4, DH };
            const float* Wps[3]  = { Wih0, Wih0, Whh0 };
            const int    lWs[3]  = { 1536, 1536, 1024 };
            const int    kofs[3] = { 0, 1024, 0 };
            const int    kcnt[3] = { 1024, 512, 1024 };

            float acc[2][4] = {{0,0,0,0},{0,0,0,0}};
            int buf = 0;
            for (int s = 0; s < 3; s++) {
                const float* Ab = Aps[s]; const int lA = lAs[s];
                const float* wrow = Wps[s] + (size_t)(wq*DH + j0 + wu)*lWs[s] + kofs[s];
                const int nch = kcnt[s] >> 4;
                float4 pa = __ldcg((const float4*)(Ab + (size_t)aB*lA + aK));
                float2 pw = __ldg((const float2*)(wrow + wK));
                __syncthreads();
                {
                    float* d = sA + (buf*16 + aK)*SA_LD + aB;
                    d[0]=pa.x; d[SA_LD]=pa.y; d[2*SA_LD]=pa.z; d[3*SA_LD]=pa.w;
                    float* dw = sW + (buf*16 + wK)*32 + wC;
                    dw[0]=pw.x; dw[32]=pw.y;
                }
                for (int ch = 0; ch < nch; ch++) {
                    __syncthreads();
                    if (ch+1 < nch) {
                        pa = __ldcg((const float4*)(Ab + (size_t)aB*lA + (ch+1)*16 + aK));
                        pw = __ldg((const float2*)(wrow + (ch+1)*16 + wK));
                    }
#pragma unroll
                    for (int kk = 0; kk < 16; kk++) {
                        float2 av = *(const float2*)(sA + (buf*16+kk)*SA_LD + tb*2);
                        float4 wv = *(const float4*)(sW + (buf*16+kk)*32 + tu*4);
                        acc[0][0]+=av.x*wv.x; acc[0][1]+=av.x*wv.y; acc[0][2]+=av.x*wv.z; acc[0][3]+=av.x*wv.w;
                        acc[1][0]+=av.y*wv.x; acc[1][1]+=av.y*wv.y; acc[1][2]+=av.y*wv.z; acc[1][3]+=av.y*wv.w;
                    }
                    if (ch+1 < nch) {
                        buf ^= 1;
                        float* d = sA + (buf*16 + aK)*SA_LD + aB;
                        d[0]=pa.x; d[SA_LD]=pa.y; d[2*SA_LD]=pa.z; d[3*SA_LD]=pa.w;
                        float* dw = sW + (buf*16 + wK)*32 + wC;
                        dw[0]=pw.x; dw[32]=pw.y;
                    }
                }
            }
            const int j = j0 + tu;
#pragma unroll
            for (int bb = 0; bb < 2; bb++) {
                int b = tb*2 + bb;
                float iv = sigf(acc[bb][0] + bia0[0]);
                float fv = sigf(acc[bb][1] + bia0[1]);
                float gv = tanhf(acc[bb][2] + bia0[2]);
                float ov = sigf(acc[bb][3] + bia0[3]);
                float cn = fv * c0reg[bb] + iv * gv;
                float hn = ov * tanhf(cn);
                c0reg[bb] = cn;
                h0n[(size_t)b*DH + j] = hn;
            }
        }
        grid_bar(DEC_NB, tgt);

        // ---------- phase B: layer-1 gates + cell ----------
        {
            const float* Aps[2]  = { h0n, h1prev };
            const float* Wps[2]  = { Wih1, Whh1 };

            float acc[2][4] = {{0,0,0,0},{0,0,0,0}};
            int buf = 0;
            for (int s = 0; s < 2; s++) {
                const float* Ab = Aps[s];
                const float* wrow = Wps[s] + (size_t)(wq*DH + j0 + wu)*1024;
                const int nch = 64;
                float4 pa = __ldcg((const float4*)(Ab + (size_t)aB*DH + aK));
                float2 pw = __ldg((const float2*)(wrow + wK));
                __syncthreads();
                {
                    float* d = sA + (buf*16 + aK)*SA_LD + aB;
                    d[0]=pa.x; d[SA_LD]=pa.y; d[2*SA_LD]=pa.z; d[3*SA_LD]=pa.w;
                    float* dw = sW + (buf*16 + wK)*32 + wC;
                    dw[0]=pw.x; dw[32]=pw.y;
                }
                for (int ch = 0; ch < nch; ch++) {
                    __syncthreads();
                    if (ch+1 < nch) {
                        pa = __ldcg((const float4*)(Ab + (size_t)aB*DH + (ch+1)*16 + aK));
                        pw = __ldg((const float2*)(wrow + (ch+1)*16 + wK));
                    }
#pragma unroll
                    for (int kk = 0; kk < 16; kk++) {
                        float2 av = *(const float2*)(sA + (buf*16+kk)*SA_LD + tb*2);
                        float4 wv = *(const float4*)(sW + (buf*16+kk)*32 + tu*4);
                        acc[0][0]+=av.x*wv.x; acc[0][1]+=av.x*wv.y; acc[0][2]+=av.x*wv.z; acc[0][3]+=av.x*wv.w;
                        acc[1][0]+=av.y*wv.x; acc[1][1]+=av.y*wv.y; acc[1][2]+=av.y*wv.z; acc[1][3]+=av.y*wv.w;
                    }
                    if (ch+1 < nch) {
                        buf ^= 1;
                        float* d = sA + (buf*16 + aK)*SA_LD + aB;
                        d[0]=pa.x; d[SA_LD]=pa.y; d[2*SA_LD]=pa.z; d[3*SA_LD]=pa.w;
                        float* dw = sW + (buf*16 + wK)*32 + wC;
                        dw[0]=pw.x; dw[32]=pw.y;
                    }
                }
            }
            const int j = j0 + tu;
#pragma unroll
            for (int bb = 0; bb < 2; bb++) {
                int b = tb*2 + bb;
                float iv = sigf(acc[bb][0] + bia1[0]);
                float fv = sigf(acc[bb][1] + bia1[1]);
                float gv = tanhf(acc[bb][2] + bia1[2]);
                float ov = sigf(acc[bb][3] + bia1[3]);
                float cn = fv * c1reg[bb] + iv * gv;
                float hn = ov * tanhf(cn);
                c1reg[bb] = cn;
                h1n[(size_t)b*DH + j] = hn;
            }
        }
        grid_bar(DEC_NB, tgt);

        // ---------- phase C: out projection + next input ----------
        {
            const int n0 = blk * 4;                 // 4 of 512 out cols
            const int ob = tid >> 2, on = tid & 3;  // thread = one (b, n)
            float accO = 0.f;
            int buf = 0;
            float4 pa = __ldcg((const float4*)(h1n + (size_t)aB*DH + aK));
            float4 pw;
            if (tid < 16) pw = __ldg((const float4*)(outW + (size_t)(n0 + (tid&3))*DH + (tid>>2)*4));
            __syncthreads();
            {
                float* d = sA + (buf*16 + aK)*SA_LD + aB;
                d[0]=pa.x; d[SA_LD]=pa.y; d[2*SA_LD]=pa.z; d[3*SA_LD]=pa.w;
                if (tid < 16) {
                    int row = tid & 3, kq = tid >> 2;
                    sWc[(buf*16 + kq*4 + 0)*4 + row] = pw.x;
                    sWc[(buf*16 + kq*4 + 1)*4 + row] = pw.y;
                    sWc[(buf*16 + kq*4 + 2)*4 + row] = pw.z;
                    sWc[(buf*16 + kq*4 + 3)*4 + row] = pw.w;
                }
            }
            for (int ch = 0; ch < 64; ch++) {
                __syncthreads();
                if (ch + 1 < 64) {
                    pa = __ldcg((const float4*)(h1n + (size_t)aB*DH + (ch+1)*16 + aK));
                    if (tid < 16)
                        pw = __ldg((const float4*)(outW + (size_t)(n0 + (tid&3))*DH + (ch+1)*16 + (tid>>2)*4));
                }
#pragma unroll
                for (int kk = 0; kk < 16; kk++)
                    accO += sA[(buf*16+kk)*SA_LD + ob] * sWc[(buf*16+kk)*4 + on];
                if (ch + 1 < 64) {
                    buf ^= 1;
                    float* d = sA + (buf*16 + aK)*SA_LD + aB;
                    d[0]=pa.x; d[SA_LD]=pa.y; d[2*SA_LD]=pa.z; d[3*SA_LD]=pa.w;
                    if (tid < 16) {
                        int row = tid & 3, kq = tid >> 2;
                        sWc[(buf*16 + kq*4 + 0)*4 + row] = pw.x;
                        sWc[(buf*16 + kq*4 + 1)*4 + row] = pw.y;
                        sWc[(buf*16 + kq*4 + 2)*4 + row] = pw.z;
                        sWc[(buf*16 + kq*4 + 3)*4 + row] = pw.w;
                    }
                }
            }
            float v = accO + __ldg(outb + n0 + on);
            out[(size_t)(ob*T + t)*J4 + n0 + on] = v;
            g_curkey[ob*J4 + n0 + on] = v;
            // refresh context part of decoder input (constant after step 0)
#pragma unroll
            for (int i = 0; i < 2; i++) {
                int idx = tid + i*256;          // 512 = 64 b x 8 cols
                int b = idx >> 3, u = blk*8 + (idx & 7);
                g_curctx[b*DH + u] = __ldg(g_ctx + b*DH + u);
            }
        }
        grid_bar(DEC_NB, tgt);
    }
}

// ---------------- launch ----------------
extern "C" void kernel_launch(void* const* d_in, const int* in_sizes, int n_in,
                              void* d_out, int out_size)
{
    const float* sa    = (const float*)d_in[0];
    const float* sb    = (const float*)d_in[1];
    const float* eWih0 = (const float*)d_in[2];
    const float* eWhh0 = (const float*)d_in[3];
    const float* eb0   = (const float*)d_in[4];
    const float* eWih1 = (const float*)d_in[5];
    const float* eWhh1 = (const float*)d_in[6];
    const float* eb1   = (const float*)d_in[7];
    const float* dWih0 = (const float*)d_in[8];
    const float* dWhh0 = (const float*)d_in[9];
    const float* db0   = (const float*)d_in[10];
    const float* dWih1 = (const float*)d_in[11];
    const float* dWhh1 = (const float*)d_in[12];
    const float* db1   = (const float*)d_in[13];
    const float* outW  = (const float*)d_in[16];
    const float* outb  = (const float*)d_in[17];
    float* out = (float*)d_out;

    float *p_xg0, *p_xg1, *p_y0, *p_y1;
    cudaGetSymbolAddress((void**)&p_xg0, g_xg0);
    cudaGetSymbolAddress((void**)&p_xg1, g_xg1);
    cudaGetSymbolAddress((void**)&p_y0,  g_y0);
    cudaGetSymbolAddress((void**)&p_y1,  g_y1);

    static int smem_set = 0;
    if (!smem_set) {
        cudaFuncSetAttribute(enc_persist, cudaFuncAttributeMaxDynamicSharedMemorySize, ENC_SMEM);
        smem_set = 1;
    }

    dim3 gemm_grid(H4 / 128, (B * S) / 128);

    for (int inp = 0; inp < 2; inp++)
        for (int dir = 0; dir < 2; dir++)
            sgemm_bias<<<gemm_grid, 256>>>(
                inp ? sb : sa,
                eWih0 + (size_t)dir * H4 * E,
                eb0 + (size_t)dir * H4,
                p_xg0 + (size_t)(inp * 2 + dir) * B * S * H4,
                B * S, H4, E);

    reset_bar<<<1, 1>>>();
    enc_persist<<<ENC_NB, 256, ENC_SMEM>>>(p_xg0, eWhh0, p_y0, 0);

    for (int inp = 0; inp < 2; inp++)
        for (int dir = 0; dir < 2; dir++)
            sgemm_bias<<<gemm_grid, 256>>>(
                p_y0 + (size_t)inp * B * S * H2,
                eWih1 + (size_t)dir * H4 * H2,
                eb1 + (size_t)dir * H4,
                p_xg1 + (size_t)(inp * 2 + dir) * B * S * H4,
                B * S, H4, H2);

    reset_bar<<<1, 1>>>();
    enc_persist<<<ENC_NB, 256, ENC_SMEM>>>(p_xg1, eWhh1, p_y1, 1);

    dec_setup<<<(B * DH + 255) / 256, 256>>>();   // also resets g_bar

    dec_persist<<<DEC_NB, 256>>>(dWih0, dWhh0, db0, dWih1, dWhh1, db1, outW, outb, out);
}

// round 5
// speedup vs baseline: 2.2764x; 1.3441x over previous
#include <cuda_runtime.h>
#include <math.h>

#define B  64
#define S  64
#define E  256
#define H  512
#define H2 1024
#define H4 2048
#define DH 1024
#define T  30
#define J4 512
#define ENC_NB 128
#define DEC_NB 128
#define SA_LD 72
#define SW_LD 36

// ---------------- device scratch ----------------
__device__ float g_xg0[4*B*S*H4];
__device__ float g_xg1[4*B*S*H4];
__device__ float g_y0[2*B*S*H2];
__device__ float g_y1[2*B*S*H2];
__device__ float g_h[2*4*B*H];     // [buf][seq][b][H]
__device__ float g_c[4*B*H];       // final c per seq (layer 1)
__device__ float g_dh0[2*B*DH];
__device__ float g_dh1[2*B*DH];
__device__ float g_curkey[B*J4];
__device__ float g_xcin[128*DH];   // rows 0..63: x0 ctx part; 64..127: sum ctx
__device__ float g_xc[128*4096];   // precomputed ctx @ Wih0[:, :1024]^T
__device__ float g_zero[4096];     // stays zero
__device__ unsigned g_bar;

__device__ __forceinline__ float sigf(float x){ return 1.f/(1.f+__expf(-x)); }

__device__ __forceinline__ void grid_bar(unsigned nb, unsigned &tgt){
    __syncthreads();
    if (threadIdx.x == 0){
        __threadfence();
        tgt += nb;
        atomicAdd(&g_bar, 1u);
        while (*((volatile unsigned*)&g_bar) < tgt) __nanosleep(32);
        __threadfence();
    }
    __syncthreads();
}

__global__ void reset_bar(){ g_bar = 0u; }

// ---------------- fp32 GEMM: C[M,N] = A[M,K] @ W[N,K]^T + bias[N] ----------------
// 128x128 tile, BK=16, double-buffered smem, prefetch distance 2.
__global__ void __launch_bounds__(256,2) sgemm_bias(
    const float* __restrict__ A, const float* __restrict__ W,
    const float* __restrict__ bias, float* __restrict__ C,
    int M, int N, int K, int ldA, int ldW)
{
    __shared__ float As[2][16][128];
    __shared__ float Ws[2][16][128];
    const int tid = threadIdx.x;
    const int tx = tid & 15, ty = tid >> 4;
    const float* Ab = A + (size_t)blockIdx.y * 128 * ldA;
    const float* Wb = W + (size_t)blockIdx.x * 128 * ldW;

    const int lrow = tid >> 1;
    const int lkq  = (tid & 1) * 8;

    float acc[8][8];
#pragma unroll
    for (int i = 0; i < 8; i++)
#pragma unroll
        for (int j = 0; j < 8; j++) acc[i][j] = 0.f;

    const int nk = K >> 4;
    float4 a0, a1, w0, w1;

    a0 = *(const float4*)(Ab + (size_t)lrow*ldA + lkq);
    a1 = *(const float4*)(Ab + (size_t)lrow*ldA + lkq + 4);
    w0 = *(const float4*)(Wb + (size_t)lrow*ldW + lkq);
    w1 = *(const float4*)(Wb + (size_t)lrow*ldW + lkq + 4);
    {
        As[0][lkq+0][lrow]=a0.x; As[0][lkq+1][lrow]=a0.y; As[0][lkq+2][lrow]=a0.z; As[0][lkq+3][lrow]=a0.w;
        As[0][lkq+4][lrow]=a1.x; As[0][lkq+5][lrow]=a1.y; As[0][lkq+6][lrow]=a1.z; As[0][lkq+7][lrow]=a1.w;
        Ws[0][lkq+0][lrow]=w0.x; Ws[0][lkq+1][lrow]=w0.y; Ws[0][lkq+2][lrow]=w0.z; Ws[0][lkq+3][lrow]=w0.w;
        Ws[0][lkq+4][lrow]=w1.x; Ws[0][lkq+5][lrow]=w1.y; Ws[0][lkq+6][lrow]=w1.z; Ws[0][lkq+7][lrow]=w1.w;
    }
    __syncthreads();
    if (nk > 1) {
        a0 = *(const float4*)(Ab + (size_t)lrow*ldA + 16 + lkq);
        a1 = *(const float4*)(Ab + (size_t)lrow*ldA + 16 + lkq + 4);
        w0 = *(const float4*)(Wb + (size_t)lrow*ldW + 16 + lkq);
        w1 = *(const float4*)(Wb + (size_t)lrow*ldW + 16 + lkq + 4);
    }

    for (int ch = 0; ch < nk; ch++) {
        if (ch + 1 < nk) {
            int b = (ch+1) & 1;
            As[b][lkq+0][lrow]=a0.x; As[b][lkq+1][lrow]=a0.y; As[b][lkq+2][lrow]=a0.z; As[b][lkq+3][lrow]=a0.w;
            As[b][lkq+4][lrow]=a1.x; As[b][lkq+5][lrow]=a1.y; As[b][lkq+6][lrow]=a1.z; As[b][lkq+7][lrow]=a1.w;
            Ws[b][lkq+0][lrow]=w0.x; Ws[b][lkq+1][lrow]=w0.y; Ws[b][lkq+2][lrow]=w0.z; Ws[b][lkq+3][lrow]=w0.w;
            Ws[b][lkq+4][lrow]=w1.x; Ws[b][lkq+5][lrow]=w1.y; Ws[b][lkq+6][lrow]=w1.z; Ws[b][lkq+7][lrow]=w1.w;
        }
        if (ch + 2 < nk) {
            int k0 = (ch+2)*16;
            a0 = *(const float4*)(Ab + (size_t)lrow*ldA + k0 + lkq);
            a1 = *(const float4*)(Ab + (size_t)lrow*ldA + k0 + lkq + 4);
            w0 = *(const float4*)(Wb + (size_t)lrow*ldW + k0 + lkq);
            w1 = *(const float4*)(Wb + (size_t)lrow*ldW + k0 + lkq + 4);
        }
        const int cb = ch & 1;
#pragma unroll
        for (int kk = 0; kk < 16; kk++) {
            float4 x0 = *(const float4*)(&As[cb][kk][ty*8 + 0]);
            float4 x1 = *(const float4*)(&As[cb][kk][ty*8 + 4]);
            float4 y0 = *(const float4*)(&Ws[cb][kk][tx*8 + 0]);
            float4 y1v= *(const float4*)(&Ws[cb][kk][tx*8 + 4]);
            float a[8] = {x0.x,x0.y,x0.z,x0.w,x1.x,x1.y,x1.z,x1.w};
            float w[8] = {y0.x,y0.y,y0.z,y0.w,y1v.x,y1v.y,y1v.z,y1v.w};
#pragma unroll
            for (int i = 0; i < 8; i++)
#pragma unroll
                for (int j = 0; j < 8; j++) acc[i][j] += a[i] * w[j];
        }
        __syncthreads();
    }

    const int m0 = blockIdx.y * 128 + ty * 8;
    const int n0 = blockIdx.x * 128 + tx * 8;
#pragma unroll
    for (int i = 0; i < 8; i++) {
        float* Cr = C + (size_t)(m0 + i) * N + n0;
#pragma unroll
        for (int j = 0; j < 8; j++) Cr[j] = acc[i][j] + bias[n0 + j];
    }
}

// ---------------- persistent encoder layer ----------------
#define ENC_SMEM ((512*64 + 2*16*SA_LD) * 4)

__global__ void __launch_bounds__(256, 1) enc_persist(
    const float* __restrict__ xg, const float* __restrict__ Whh,
    float* __restrict__ y, int write_final_c)
{
    extern __shared__ float sm[];
    float* sW = sm;                 // [512][64]
    float* sA = sm + 512*64;        // [2][16][SA_LD]

    const int blk = blockIdx.x;
    const int seq = blk >> 5, tile = blk & 31;
    const int inp = seq >> 1, dir = seq & 1;
    const int j0 = tile * 16;
    const int tid = threadIdx.x;
    const int tu = tid & 15;
    const int tb = tid >> 4;
    unsigned tgt = 0;

    const float* Wd  = Whh + (size_t)dir * H4 * H;
    const float* xgb = xg + (size_t)seq * B * S * H4;

    {   // one-time W slice -> smem (k-major, cols interleaved unit-major c=u*4+q)
        int c = tid & 63;
        int kbase = (tid >> 6) * 128;
        int q = c & 3, u = c >> 2;
        const float* src = Wd + (size_t)(q * H + j0 + u) * H + kbase;
        for (int i = 0; i < 128; i += 4) {
            float4 v = __ldg((const float4*)(src + i));
            sW[(kbase+i+0)*64 + c] = v.x;
            sW[(kbase+i+1)*64 + c] = v.y;
            sW[(kbase+i+2)*64 + c] = v.z;
            sW[(kbase+i+3)*64 + c] = v.w;
        }
    }
    {   // zero h buffer 0 slice
        int u = tid & 15, b0 = (tid >> 4) * 4;
        for (int i = 0; i < 4; i++)
            g_h[(size_t)seq*B*H + (size_t)(b0+i)*H + j0 + u] = 0.f;
    }
    float creg[4] = {0.f,0.f,0.f,0.f};
    grid_bar(ENC_NB, tgt);

    const int aB = tid & 63;
    const int aK = (tid >> 6) * 4;

    for (int t = 0; t < S; t++) {
        const int pos = dir ? (S-1-t) : t;
        const float* hprev = g_h + (size_t)(t&1)*4*B*H + (size_t)seq*B*H;
        float* hnext       = g_h + (size_t)((t+1)&1)*4*B*H + (size_t)seq*B*H;
        const float* hb = hprev + (size_t)aB*H + aK;

        float xgv[4][4];
#pragma unroll
        for (int bb = 0; bb < 4; bb++) {
            const float* xr = xgb + (size_t)((tb*4+bb)*S + pos)*H4 + j0 + tu;
#pragma unroll
            for (int q = 0; q < 4; q++) xgv[bb][q] = __ldg(xr + q*H);
        }

        float acc[4][4];
#pragma unroll
        for (int i = 0; i < 4; i++)
#pragma unroll
            for (int j = 0; j < 4; j++) acc[i][j] = 0.f;

        float4 pa = __ldcg((const float4*)(hb));
        {
            float* d = sA + aK*SA_LD + aB;
            d[0]=pa.x; d[SA_LD]=pa.y; d[2*SA_LD]=pa.z; d[3*SA_LD]=pa.w;
        }
        __syncthreads();
        pa = __ldcg((const float4*)(hb + 16));

        for (int ch = 0; ch < 32; ch++) {
            if (ch + 1 < 32) {
                float* d = sA + (((ch+1)&1)*16 + aK)*SA_LD + aB;
                d[0]=pa.x; d[SA_LD]=pa.y; d[2*SA_LD]=pa.z; d[3*SA_LD]=pa.w;
            }
            if (ch + 2 < 32)
                pa = __ldcg((const float4*)(hb + (ch+2)*16));
            const float* ab = sA + ((ch&1)*16)*SA_LD;
            const float* wb = sW + (ch*16)*64;
#pragma unroll
            for (int kk = 0; kk < 16; kk++) {
                float4 av = *(const float4*)(ab + kk*SA_LD + tb*4);
                float4 wv = *(const float4*)(wb + kk*64 + tu*4);
                acc[0][0] += av.x*wv.x; acc[0][1] += av.x*wv.y; acc[0][2] += av.x*wv.z; acc[0][3] += av.x*wv.w;
                acc[1][0] += av.y*wv.x; acc[1][1] += av.y*wv.y; acc[1][2] += av.y*wv.z; acc[1][3] += av.y*wv.w;
                acc[2][0] += av.z*wv.x; acc[2][1] += av.z*wv.y; acc[2][2] += av.z*wv.z; acc[2][3] += av.z*wv.w;
                acc[3][0] += av.w*wv.x; acc[3][1] += av.w*wv.y; acc[3][2] += av.w*wv.z; acc[3][3] += av.w*wv.w;
            }
            __syncthreads();
        }

        const int j = j0 + tu;
#pragma unroll
        for (int bb = 0; bb < 4; bb++) {
            int b = tb*4 + bb;
            float iv = sigf(acc[bb][0] + xgv[bb][0]);
            float fv = sigf(acc[bb][1] + xgv[bb][1]);
            float gv = tanhf(acc[bb][2] + xgv[bb][2]);
            float ov = sigf(acc[bb][3] + xgv[bb][3]);
            float cn = fv * creg[bb] + iv * gv;
            float hn = ov * tanhf(cn);
            creg[bb] = cn;
            hnext[(size_t)b*H + j] = hn;
            y[(size_t)(inp*B*S + b*S + pos)*H2 + dir*H + j] = hn;
        }
        grid_bar(ENC_NB, tgt);
    }

    if (write_final_c) {
#pragma unroll
        for (int bb = 0; bb < 4; bb++)
            g_c[(size_t)seq*B*H + (size_t)(tb*4+bb)*H + j0 + tu] = creg[bb];
    }
}

// ---------------- decoder setup ----------------
__global__ void dec_setup()
{
    if (blockIdx.x == 0 && threadIdx.x == 0) g_bar = 0u;
    int idx = blockIdx.x * blockDim.x + threadIdx.x;   // over B*DH
    if (idx >= B * DH) return;
    int b = idx / DH, u = idx % DH;

    float s = 0.f;
    for (int t = 0; t < S; t++) s += g_y1[(size_t)(b * S + t) * H2 + u];
    g_xcin[(size_t)(64 + b) * DH + u] = s;                          // constant context
    g_xcin[(size_t)b * DH + u] = g_y1[(size_t)(b * S + S - 1) * H2 + u];  // step-0 ctx part

    if (u < J4) g_curkey[b * J4 + u] = g_y1[(size_t)(B * S + b * S + 0) * H2 + u];

    float hv;
    if (u < H) hv = g_h[(size_t)1 * B * H + (size_t)b * H + u];
    else       hv = g_h[(size_t)3 * B * H + (size_t)b * H + (u - H)];
    g_dh0[idx] = hv;
    g_dh1[idx] = hv;
}

// ---------------- persistent decoder ----------------
__device__ __forceinline__ void dec_seg(
    const float* __restrict__ Ab, int lA,
    const float* __restrict__ wrow, int nch,
    float acc[2][4], float* sA, float* sW,
    int tb, int tu, int aB, int aK, int wC, int wK2)
{
    float4 pa = __ldcg((const float4*)(Ab + (size_t)aB*lA + aK));
    float2 pw = __ldg((const float2*)(wrow + wK2));
    __syncthreads();
    {
        float* d = sA + aK*SA_LD + aB;
        d[0]=pa.x; d[SA_LD]=pa.y; d[2*SA_LD]=pa.z; d[3*SA_LD]=pa.w;
        sW[(wK2+0)*SW_LD + wC] = pw.x;
        sW[(wK2+1)*SW_LD + wC] = pw.y;
    }
    __syncthreads();
    if (nch > 1) {
        pa = __ldcg((const float4*)(Ab + (size_t)aB*lA + 16 + aK));
        pw = __ldg((const float2*)(wrow + 16 + wK2));
    }
    for (int ch = 0; ch < nch; ch++) {
        if (ch + 1 < nch) {
            int bs = ((ch+1)&1)*16;
            float* d = sA + (bs + aK)*SA_LD + aB;
            d[0]=pa.x; d[SA_LD]=pa.y; d[2*SA_LD]=pa.z; d[3*SA_LD]=pa.w;
            sW[(bs + wK2+0)*SW_LD + wC] = pw.x;
            sW[(bs + wK2+1)*SW_LD + wC] = pw.y;
        }
        if (ch + 2 < nch) {
            pa = __ldcg((const float4*)(Ab + (size_t)aB*lA + (ch+2)*16 + aK));
            pw = __ldg((const float2*)(wrow + (ch+2)*16 + wK2));
        }
        const float* ab = sA + ((ch&1)*16)*SA_LD;
        const float* wb = sW + ((ch&1)*16)*SW_LD;
#pragma unroll
        for (int kk = 0; kk < 16; kk++) {
            float2 av = *(const float2*)(ab + kk*SA_LD + tb*2);
            float4 wv = *(const float4*)(wb + kk*SW_LD + tu*4);
            acc[0][0]+=av.x*wv.x; acc[0][1]+=av.x*wv.y; acc[0][2]+=av.x*wv.z; acc[0][3]+=av.x*wv.w;
            acc[1][0]+=av.y*wv.x; acc[1][1]+=av.y*wv.y; acc[1][2]+=av.y*wv.z; acc[1][3]+=av.y*wv.w;
        }
        __syncthreads();
    }
}

__global__ void __launch_bounds__(256, 1) dec_persist(
    const float* __restrict__ Wih0, const float* __restrict__ Whh0, const float* __restrict__ b0,
    const float* __restrict__ Wih1, const float* __restrict__ Whh1, const float* __restrict__ b1,
    const float* __restrict__ outW, const float* __restrict__ outb,
    float* __restrict__ out)
{
    __shared__ float sA[2*16*SA_LD];
    __shared__ float sW[2*16*SW_LD];
    __shared__ float sWc[2*16*4];

    const int blk = blockIdx.x;
    const int j0 = blk * 8;
    const int tid = threadIdx.x;
    const int tu = tid & 7;
    const int tb = tid >> 3;
    unsigned tgt = 0;

    const int aB = tid & 63, aK = (tid >> 6) * 4;
    const int wC = tid >> 3, wK2 = (tid & 7) * 2;
    const int wq = wC & 3, wu = wC >> 2;
    const int wrowi = wq*DH + j0 + wu;

    const float* wA_key = Wih0 + (size_t)wrowi * 1536 + 1024;
    const float* wA_h   = Whh0 + (size_t)wrowi * 1024;
    const float* wB_x   = Wih1 + (size_t)wrowi * 1024;
    const float* wB_h   = Whh1 + (size_t)wrowi * 1024;

    float c0reg[2], c1reg[2];
#pragma unroll
    for (int bb = 0; bb < 2; bb++) {
        int b = tb*2 + bb;
        int u = j0 + tu;
        float cv = (u < H) ? g_c[(size_t)1*B*H + (size_t)b*H + u]
                           : g_c[(size_t)3*B*H + (size_t)b*H + (u - H)];
        c0reg[bb] = cv; c1reg[bb] = cv;
    }
    float bia0[4], bia1[4];
    {
        int j = j0 + tu;
#pragma unroll
        for (int q = 0; q < 4; q++) { bia0[q] = __ldg(b0 + q*DH + j); bia1[q] = __ldg(b1 + q*DH + j); }
    }

    for (int t = 0; t < T; t++) {
        const float* h0prev = g_dh0 + (size_t)(t&1)*B*DH;
        float* h0n          = g_dh0 + (size_t)((t+1)&1)*B*DH;
        const float* h1prev = g_dh1 + (size_t)(t&1)*B*DH;
        float* h1n          = g_dh1 + (size_t)((t+1)&1)*B*DH;

        // ---------- phase A: layer-0 gates + cell (ctx folded into g_xc) ----------
        {
            const float* xcb = g_xc + (size_t)(t > 0 ? 64 : 0) * 4096;
            float xcv[2][4];
#pragma unroll
            for (int bb = 0; bb < 2; bb++)
#pragma unroll
                for (int q = 0; q < 4; q++)
                    xcv[bb][q] = __ldg(xcb + (size_t)(tb*2+bb)*4096 + q*DH + j0 + tu);

            float acc[2][4] = {{0,0,0,0},{0,0,0,0}};
            dec_seg(g_curkey, J4, wA_key, 32, acc, sA, sW, tb, tu, aB, aK, wC, wK2);
            dec_seg(h0prev,   DH, wA_h,   64, acc, sA, sW, tb, tu, aB, aK, wC, wK2);

            const int j = j0 + tu;
#pragma unroll
            for (int bb = 0; bb < 2; bb++) {
                int b = tb*2 + bb;
                float iv = sigf(acc[bb][0] + bia0[0] + xcv[bb][0]);
                float fv = sigf(acc[bb][1] + bia0[1] + xcv[bb][1]);
                float gv = tanhf(acc[bb][2] + bia0[2] + xcv[bb][2]);
                float ov = sigf(acc[bb][3] + bia0[3] + xcv[bb][3]);
                float cn = fv * c0reg[bb] + iv * gv;
                float hn = ov * tanhf(cn);
                c0reg[bb] = cn;
                h0n[(size_t)b*DH + j] = hn;
            }
        }
        grid_bar(DEC_NB, tgt);

        // ---------- phase B: layer-1 gates + cell ----------
        {
            float acc[2][4] = {{0,0,0,0},{0,0,0,0}};
            dec_seg(h0n,    DH, wB_x, 64, acc, sA, sW, tb, tu, aB, aK, wC, wK2);
            dec_seg(h1prev, DH, wB_h, 64, acc, sA, sW, tb, tu, aB, aK, wC, wK2);

            const int j = j0 + tu;
#pragma unroll
            for (int bb = 0; bb < 2; bb++) {
                int b = tb*2 + bb;
                float iv = sigf(acc[bb][0] + bia1[0]);
                float fv = sigf(acc[bb][1] + bia1[1]);
                float gv = tanhf(acc[bb][2] + bia1[2]);
                float ov = sigf(acc[bb][3] + bia1[3]);
                float cn = fv * c1reg[bb] + iv * gv;
                float hn = ov * tanhf(cn);
                c1reg[bb] = cn;
                h1n[(size_t)b*DH + j] = hn;
            }
        }
        grid_bar(DEC_NB, tgt);

        // ---------- phase C: out projection + next keyframe ----------
        {
            const int n0 = blk * 4;
            const int ob = tid >> 2, on = tid & 3;
            float accO = 0.f;

            float4 pa = __ldcg((const float4*)(h1n + (size_t)aB*DH + aK));
            float4 pw;
            if (tid < 16) pw = __ldg((const float4*)(outW + (size_t)(n0 + (tid&3))*DH + (tid>>2)*4));
            __syncthreads();
            {
                float* d = sA + aK*SA_LD + aB;
                d[0]=pa.x; d[SA_LD]=pa.y; d[2*SA_LD]=pa.z; d[3*SA_LD]=pa.w;
                if (tid < 16) {
                    int col = tid & 3, kq = (tid >> 2) * 4;
                    sWc[(kq+0)*4 + col] = pw.x;
                    sWc[(kq+1)*4 + col] = pw.y;
                    sWc[(kq+2)*4 + col] = pw.z;
                    sWc[(kq+3)*4 + col] = pw.w;
                }
            }
            __syncthreads();
            pa = __ldcg((const float4*)(h1n + (size_t)aB*DH + 16 + aK));
            if (tid < 16) pw = __ldg((const float4*)(outW + (size_t)(n0 + (tid&3))*DH + 16 + (tid>>2)*4));

            for (int ch = 0; ch < 64; ch++) {
                if (ch + 1 < 64) {
                    int bs = ((ch+1)&1)*16;
                    float* d = sA + (bs + aK)*SA_LD + aB;
                    d[0]=pa.x; d[SA_LD]=pa.y; d[2*SA_LD]=pa.z; d[3*SA_LD]=pa.w;
                    if (tid < 16) {
                        int col = tid & 3, kq = (tid >> 2) * 4;
                        sWc[(bs+kq+0)*4 + col] = pw.x;
                        sWc[(bs+kq+1)*4 + col] = pw.y;
                        sWc[(bs+kq+2)*4 + col] = pw.z;
                        sWc[(bs+kq+3)*4 + col] = pw.w;
                    }
                }
                if (ch + 2 < 64) {
                    pa = __ldcg((const float4*)(h1n + (size_t)aB*DH + (ch+2)*16 + aK));
                    if (tid < 16) pw = __ldg((const float4*)(outW + (size_t)(n0 + (tid&3))*DH + (ch+2)*16 + (tid>>2)*4));
                }
                const int bs = (ch&1)*16;
#pragma unroll
                for (int kk = 0; kk < 16; kk++)
                    accO += sA[(bs+kk)*SA_LD + ob] * sWc[(bs+kk)*4 + on];
                __syncthreads();
            }
            float v = accO + __ldg(outb + n0 + on);
            out[(size_t)(ob*T + t)*J4 + n0 + on] = v;
            g_curkey[ob*J4 + n0 + on] = v;
        }
        grid_bar(DEC_NB, tgt);
    }
}

// ---------------- launch ----------------
extern "C" void kernel_launch(void* const* d_in, const int* in_sizes, int n_in,
                              void* d_out, int out_size)
{
    const float* sa    = (const float*)d_in[0];
    const float* sb    = (const float*)d_in[1];
    const float* eWih0 = (const float*)d_in[2];
    const float* eWhh0 = (const float*)d_in[3];
    const float* eb0   = (const float*)d_in[4];
    const float* eWih1 = (const float*)d_in[5];
    const float* eWhh1 = (const float*)d_in[6];
    const float* eb1   = (const float*)d_in[7];
    const float* dWih0 = (const float*)d_in[8];
    const float* dWhh0 = (const float*)d_in[9];
    const float* db0   = (const float*)d_in[10];
    const float* dWih1 = (const float*)d_in[11];
    const float* dWhh1 = (const float*)d_in[12];
    const float* db1   = (const float*)d_in[13];
    const float* outW  = (const float*)d_in[16];
    const float* outb  = (const float*)d_in[17];
    float* out = (float*)d_out;

    float *p_xg0, *p_xg1, *p_y0, *p_y1, *p_xcin, *p_xc, *p_zero;
    cudaGetSymbolAddress((void**)&p_xg0,  g_xg0);
    cudaGetSymbolAddress((void**)&p_xg1,  g_xg1);
    cudaGetSymbolAddress((void**)&p_y0,   g_y0);
    cudaGetSymbolAddress((void**)&p_y1,   g_y1);
    cudaGetSymbolAddress((void**)&p_xcin, g_xcin);
    cudaGetSymbolAddress((void**)&p_xc,   g_xc);
    cudaGetSymbolAddress((void**)&p_zero, g_zero);

    cudaFuncSetAttribute(enc_persist, cudaFuncAttributeMaxDynamicSharedMemorySize, ENC_SMEM);

    dim3 gemm_grid(H4 / 128, (B * S) / 128);

    for (int inp = 0; inp < 2; inp++)
        for (int dir = 0; dir < 2; dir++)
            sgemm_bias<<<gemm_grid, 256>>>(
                inp ? sb : sa,
                eWih0 + (size_t)dir * H4 * E,
                eb0 + (size_t)dir * H4,
                p_xg0 + (size_t)(inp * 2 + dir) * B * S * H4,
                B * S, H4, E, E, E);

    reset_bar<<<1, 1>>>();
    enc_persist<<<ENC_NB, 256, ENC_SMEM>>>(p_xg0, eWhh0, p_y0, 0);

    for (int inp = 0; inp < 2; inp++)
        for (int dir = 0; dir < 2; dir++)
            sgemm_bias<<<gemm_grid, 256>>>(
                p_y0 + (size_t)inp * B * S * H2,
                eWih1 + (size_t)dir * H4 * H2,
                eb1 + (size_t)dir * H4,
                p_xg1 + (size_t)(inp * 2 + dir) * B * S * H4,
                B * S, H4, H2, H2, H2);

    reset_bar<<<1, 1>>>();
    enc_persist<<<ENC_NB, 256, ENC_SMEM>>>(p_xg1, eWhh1, p_y1, 1);

    dec_setup<<<(B * DH + 255) / 256, 256>>>();   // resets g_bar, fills g_xcin

    // xc = [x0ctx; ctx] @ dec_Wih0[:, :1024]^T  (M=128, N=4096, K=1024)
    sgemm_bias<<<dim3(4096/128, 1), 256>>>(p_xcin, dWih0, p_zero, p_xc,
                                           128, 4096, 1024, 1024, 1536);

    dec_persist<<<DEC_NB, 256>>>(dWih0, dWhh0, db0, dWih1, dWhh1, db1, outW, outb, out);
}

// round 7
// speedup vs baseline: 2.3030x; 1.0117x over previous
#include <cuda_runtime.h>
#include <math.h>

#define B  64
#define S  64
#define E  256
#define H  512
#define H2 1024
#define H4 2048
#define DH 1024
#define T  30
#define J4 512
#define ENC_NB 128
#define DEC_NB 128
#define SA_LD 72
#define SW_LD 36

typedef unsigned long long u64;

// ---------------- device scratch ----------------
__device__ float g_xg0[4*B*S*H4];
__device__ float g_xg1[4*B*S*H4];
__device__ float g_y0[2*B*S*H2];
__device__ float g_y1[2*B*S*H2];
__device__ float g_h[2*4*B*H];     // [buf][seq][b][H]
__device__ float g_c[4*B*H];       // final c per seq (layer 1)
__device__ float g_dh0[2*B*DH];
__device__ float g_dh1[2*B*DH];
__device__ float g_curkey[B*J4];
__device__ float g_xcin[128*DH];   // rows 0..63: x0 ctx part; 64..127: sum ctx
__device__ float g_xc[128*4096];   // precomputed ctx @ Wih0[:, :1024]^T
__device__ float g_zero[4096];     // stays zero
__device__ unsigned g_bar;
__device__ unsigned g_bars[4];     // per-seq encoder barriers

__device__ __forceinline__ float sigf(float x){ return 1.f/(1.f+__expf(-x)); }

// packed f32x2 helpers (Blackwell FFMA2 path)
__device__ __forceinline__ u64 ffma2(u64 a, u64 b, u64 c){
    u64 d;
    asm("fma.rn.f32x2 %0, %1, %2, %3;" : "=l"(d) : "l"(a), "l"(b), "l"(c));
    return d;
}
__device__ __forceinline__ u64 dup2(float x){
    u64 d;
    asm("mov.b64 %0, {%1, %1};" : "=l"(d) : "f"(x));
    return d;
}
__device__ __forceinline__ float2 unpk(u64 d){
    float2 r;
    asm("mov.b64 {%0, %1}, %2;" : "=f"(r.x), "=f"(r.y) : "l"(d));
    return r;
}

__device__ __forceinline__ void bar_sync(unsigned* ctr, unsigned nb, unsigned &tgt){
    __syncthreads();
    if (threadIdx.x == 0){
        __threadfence();
        tgt += nb;
        atomicAdd(ctr, 1u);
        while (*((volatile unsigned*)ctr) < tgt) __nanosleep(32);
        __threadfence();
    }
    __syncthreads();
}

__global__ void reset_bar(){
    g_bar = 0u;
    if (threadIdx.x < 4) g_bars[threadIdx.x] = 0u;
}

// ---------------- fp32 GEMM: C[M,N] = A[M,K] @ W[N,K]^T + bias[N] ----------------
// 128x128 tile, BK=16, double-buffered smem, prefetch distance 2, FFMA2 core.
__global__ void __launch_bounds__(256,2) sgemm_bias(
    const float* __restrict__ A, const float* __restrict__ W,
    const float* __restrict__ bias, float* __restrict__ C,
    int M, int N, int K, int ldA, int ldW)
{
    __shared__ float As[2][16][128];
    __shared__ float Ws[2][16][128];
    const int tid = threadIdx.x;
    const int tx = tid & 15, ty = tid >> 4;
    const float* Ab = A + (size_t)blockIdx.y * 128 * ldA;
    const float* Wb = W + (size_t)blockIdx.x * 128 * ldW;

    const int lrow = tid >> 1;
    const int lkq  = (tid & 1) * 8;

    u64 acc2[8][4];
    const u64 z2 = dup2(0.f);
#pragma unroll
    for (int i = 0; i < 8; i++)
#pragma unroll
        for (int j = 0; j < 4; j++) acc2[i][j] = z2;

    const int nk = K >> 4;
    float4 a0, a1, w0, w1;

    a0 = *(const float4*)(Ab + (size_t)lrow*ldA + lkq);
    a1 = *(const float4*)(Ab + (size_t)lrow*ldA + lkq + 4);
    w0 = *(const float4*)(Wb + (size_t)lrow*ldW + lkq);
    w1 = *(const float4*)(Wb + (size_t)lrow*ldW + lkq + 4);
    {
        As[0][lkq+0][lrow]=a0.x; As[0][lkq+1][lrow]=a0.y; As[0][lkq+2][lrow]=a0.z; As[0][lkq+3][lrow]=a0.w;
        As[0][lkq+4][lrow]=a1.x; As[0][lkq+5][lrow]=a1.y; As[0][lkq+6][lrow]=a1.z; As[0][lkq+7][lrow]=a1.w;
        Ws[0][lkq+0][lrow]=w0.x; Ws[0][lkq+1][lrow]=w0.y; Ws[0][lkq+2][lrow]=w0.z; Ws[0][lkq+3][lrow]=w0.w;
        Ws[0][lkq+4][lrow]=w1.x; Ws[0][lkq+5][lrow]=w1.y; Ws[0][lkq+6][lrow]=w1.z; Ws[0][lkq+7][lrow]=w1.w;
    }
    __syncthreads();
    if (nk > 1) {
        a0 = *(const float4*)(Ab + (size_t)lrow*ldA + 16 + lkq);
        a1 = *(const float4*)(Ab + (size_t)lrow*ldA + 16 + lkq + 4);
        w0 = *(const float4*)(Wb + (size_t)lrow*ldW + 16 + lkq);
        w1 = *(const float4*)(Wb + (size_t)lrow*ldW + 16 + lkq + 4);
    }

    for (int ch = 0; ch < nk; ch++) {
        if (ch + 1 < nk) {
            int b = (ch+1) & 1;
            As[b][lkq+0][lrow]=a0.x; As[b][lkq+1][lrow]=a0.y; As[b][lkq+2][lrow]=a0.z; As[b][lkq+3][lrow]=a0.w;
            As[b][lkq+4][lrow]=a1.x; As[b][lkq+5][lrow]=a1.y; As[b][lkq+6][lrow]=a1.z; As[b][lkq+7][lrow]=a1.w;
            Ws[b][lkq+0][lrow]=w0.x; Ws[b][lkq+1][lrow]=w0.y; Ws[b][lkq+2][lrow]=w0.z; Ws[b][lkq+3][lrow]=w0.w;
            Ws[b][lkq+4][lrow]=w1.x; Ws[b][lkq+5][lrow]=w1.y; Ws[b][lkq+6][lrow]=w1.z; Ws[b][lkq+7][lrow]=w1.w;
        }
        if (ch + 2 < nk) {
            int k0 = (ch+2)*16;
            a0 = *(const float4*)(Ab + (size_t)lrow*ldA + k0 + lkq);
            a1 = *(const float4*)(Ab + (size_t)lrow*ldA + k0 + lkq + 4);
            w0 = *(const float4*)(Wb + (size_t)lrow*ldW + k0 + lkq);
            w1 = *(const float4*)(Wb + (size_t)lrow*ldW + k0 + lkq + 4);
        }
        const int cb = ch & 1;
#pragma unroll
        for (int kk = 0; kk < 16; kk++) {
            float4 x0 = *(const float4*)(&As[cb][kk][ty*8 + 0]);
            float4 x1 = *(const float4*)(&As[cb][kk][ty*8 + 4]);
            const u64* wp = (const u64*)(&Ws[cb][kk][tx*8]);
            u64 wq0 = wp[0], wq1 = wp[1], wq2 = wp[2], wq3 = wp[3];
            float a[8] = {x0.x,x0.y,x0.z,x0.w,x1.x,x1.y,x1.z,x1.w};
#pragma unroll
            for (int i = 0; i < 8; i++) {
                u64 ad = dup2(a[i]);
                acc2[i][0] = ffma2(ad, wq0, acc2[i][0]);
                acc2[i][1] = ffma2(ad, wq1, acc2[i][1]);
                acc2[i][2] = ffma2(ad, wq2, acc2[i][2]);
                acc2[i][3] = ffma2(ad, wq3, acc2[i][3]);
            }
        }
        __syncthreads();
    }

    const int m0 = blockIdx.y * 128 + ty * 8;
    const int n0 = blockIdx.x * 128 + tx * 8;
#pragma unroll
    for (int i = 0; i < 8; i++) {
        float* Cr = C + (size_t)(m0 + i) * N + n0;
#pragma unroll
        for (int jp = 0; jp < 4; jp++) {
            float2 e = unpk(acc2[i][jp]);
            Cr[2*jp+0] = e.x + bias[n0 + 2*jp+0];
            Cr[2*jp+1] = e.y + bias[n0 + 2*jp+1];
        }
    }
}

// ---------------- persistent encoder layer ----------------
#define ENC_SMEM ((512*64 + 2*16*SA_LD) * 4)

__global__ void __launch_bounds__(256, 1) enc_persist(
    const float* __restrict__ xg, const float* __restrict__ Whh,
    float* __restrict__ y, int write_final_c)
{
    extern __shared__ float sm[];
    float* sW = sm;                 // [512][64]
    float* sA = sm + 512*64;        // [2][16][SA_LD]

    const int blk = blockIdx.x;
    const int seq = blk >> 5, tile = blk & 31;
    const int inp = seq >> 1, dir = seq & 1;
    const int j0 = tile * 16;
    const int tid = threadIdx.x;
    const int tu = tid & 15;
    const int tb = tid >> 4;
    unsigned tgt = 0;
    unsigned* myctr = &g_bars[seq];

    const float* Wd  = Whh + (size_t)dir * H4 * H;
    const float* xgb = xg + (size_t)seq * B * S * H4;

    {   // one-time W slice -> smem (k-major, cols interleaved unit-major c=u*4+q)
        int c = tid & 63;
        int kbase = (tid >> 6) * 128;
        int q = c & 3, u = c >> 2;
        const float* src = Wd + (size_t)(q * H + j0 + u) * H + kbase;
        for (int i = 0; i < 128; i += 4) {
            float4 v = __ldg((const float4*)(src + i));
            sW[(kbase+i+0)*64 + c] = v.x;
            sW[(kbase+i+1)*64 + c] = v.y;
            sW[(kbase+i+2)*64 + c] = v.z;
            sW[(kbase+i+3)*64 + c] = v.w;
        }
    }
    {   // zero h buffer 0 slice
        int u = tid & 15, b0 = (tid >> 4) * 4;
        for (int i = 0; i < 4; i++)
            g_h[(size_t)seq*B*H + (size_t)(b0+i)*H + j0 + u] = 0.f;
    }
    float creg[4] = {0.f,0.f,0.f,0.f};
    bar_sync(myctr, 32, tgt);

    const int aB = tid & 63;
    const int aK = (tid >> 6) * 4;
    const u64 z2 = dup2(0.f);

    for (int t = 0; t < S; t++) {
        const int pos = dir ? (S-1-t) : t;
        const float* hprev = g_h + (size_t)(t&1)*4*B*H + (size_t)seq*B*H;
        float* hnext       = g_h + (size_t)((t+1)&1)*4*B*H + (size_t)seq*B*H;
        const float* hb = hprev + (size_t)aB*H + aK;

        float xgv[4][4];
#pragma unroll
        for (int bb = 0; bb < 4; bb++) {
            const float* xr = xgb + (size_t)((tb*4+bb)*S + pos)*H4 + j0 + tu;
#pragma unroll
            for (int q = 0; q < 4; q++) xgv[bb][q] = __ldg(xr + q*H);
        }

        u64 acc2[4][2];
#pragma unroll
        for (int i = 0; i < 4; i++) { acc2[i][0] = z2; acc2[i][1] = z2; }

        float4 pa = __ldcg((const float4*)(hb));
        {
            float* d = sA + aK*SA_LD + aB;
            d[0]=pa.x; d[SA_LD]=pa.y; d[2*SA_LD]=pa.z; d[3*SA_LD]=pa.w;
        }
        __syncthreads();
        pa = __ldcg((const float4*)(hb + 16));

        for (int ch = 0; ch < 32; ch++) {
            if (ch + 1 < 32) {
                float* d = sA + (((ch+1)&1)*16 + aK)*SA_LD + aB;
                d[0]=pa.x; d[SA_LD]=pa.y; d[2*SA_LD]=pa.z; d[3*SA_LD]=pa.w;
            }
            if (ch + 2 < 32)
                pa = __ldcg((const float4*)(hb + (ch+2)*16));
            const float* ab = sA + ((ch&1)*16)*SA_LD;
            const float* wb = sW + (ch*16)*64;
#pragma unroll
            for (int kk = 0; kk < 16; kk++) {
                float4 av = *(const float4*)(ab + kk*SA_LD + tb*4);
                const u64* wp = (const u64*)(wb + kk*64 + tu*4);
                u64 wv0 = wp[0], wv1 = wp[1];           // gates (i,f), (g,o)
                u64 a0d = dup2(av.x), a1d = dup2(av.y), a2d = dup2(av.z), a3d = dup2(av.w);
                acc2[0][0] = ffma2(a0d, wv0, acc2[0][0]); acc2[0][1] = ffma2(a0d, wv1, acc2[0][1]);
                acc2[1][0] = ffma2(a1d, wv0, acc2[1][0]); acc2[1][1] = ffma2(a1d, wv1, acc2[1][1]);
                acc2[2][0] = ffma2(a2d, wv0, acc2[2][0]); acc2[2][1] = ffma2(a2d, wv1, acc2[2][1]);
                acc2[3][0] = ffma2(a3d, wv0, acc2[3][0]); acc2[3][1] = ffma2(a3d, wv1, acc2[3][1]);
            }
            __syncthreads();
        }

        const int j = j0 + tu;
#pragma unroll
        for (int bb = 0; bb < 4; bb++) {
            int b = tb*4 + bb;
            float2 gif = unpk(acc2[bb][0]);
            float2 ggo = unpk(acc2[bb][1]);
            float iv = sigf(gif.x + xgv[bb][0]);
            float fv = sigf(gif.y + xgv[bb][1]);
            float gv = tanhf(ggo.x + xgv[bb][2]);
            float ov = sigf(ggo.y + xgv[bb][3]);
            float cn = fv * creg[bb] + iv * gv;
            float hn = ov * tanhf(cn);
            creg[bb] = cn;
            hnext[(size_t)b*H + j] = hn;
            y[(size_t)(inp*B*S + b*S + pos)*H2 + dir*H + j] = hn;
        }
        bar_sync(myctr, 32, tgt);
    }

    if (write_final_c) {
#pragma unroll
        for (int bb = 0; bb < 4; bb++)
            g_c[(size_t)seq*B*H + (size_t)(tb*4+bb)*H + j0 + tu] = creg[bb];
    }
}

// ---------------- decoder setup ----------------
__global__ void dec_setup()
{
    if (blockIdx.x == 0 && threadIdx.x == 0) g_bar = 0u;
    int idx = blockIdx.x * blockDim.x + threadIdx.x;   // over B*DH
    if (idx >= B * DH) return;
    int b = idx / DH, u = idx % DH;

    float s = 0.f;
    for (int t = 0; t < S; t++) s += g_y1[(size_t)(b * S + t) * H2 + u];
    g_xcin[(size_t)(64 + b) * DH + u] = s;                          // constant context
    g_xcin[(size_t)b * DH + u] = g_y1[(size_t)(b * S + S - 1) * H2 + u];  // step-0 ctx part

    if (u < J4) g_curkey[b * J4 + u] = g_y1[(size_t)(B * S + b * S + 0) * H2 + u];

    float hv;
    if (u < H) hv = g_h[(size_t)1 * B * H + (size_t)b * H + u];
    else       hv = g_h[(size_t)3 * B * H + (size_t)b * H + (u - H)];
    g_dh0[idx] = hv;
    g_dh1[idx] = hv;
}

// ---------------- persistent decoder ----------------
__device__ __forceinline__ void dec_seg(
    const float* __restrict__ Ab, int lA,
    const float* __restrict__ wrow, int nch,
    u64 acc2[2][2], float* sA, float* sW,
    int tb, int tu, int aB, int aK, int wC, int wK2)
{
    float4 pa = __ldcg((const float4*)(Ab + (size_t)aB*lA + aK));
    float2 pw = __ldg((const float2*)(wrow + wK2));
    __syncthreads();
    {
        float* d = sA + aK*SA_LD + aB;
        d[0]=pa.x; d[SA_LD]=pa.y; d[2*SA_LD]=pa.z; d[3*SA_LD]=pa.w;
        sW[(wK2+0)*SW_LD + wC] = pw.x;
        sW[(wK2+1)*SW_LD + wC] = pw.y;
    }
    __syncthreads();
    if (nch > 1) {
        pa = __ldcg((const float4*)(Ab + (size_t)aB*lA + 16 + aK));
        pw = __ldg((const float2*)(wrow + 16 + wK2));
    }
    for (int ch = 0; ch < nch; ch++) {
        if (ch + 1 < nch) {
            int bs = ((ch+1)&1)*16;
            float* d = sA + (bs + aK)*SA_LD + aB;
            d[0]=pa.x; d[SA_LD]=pa.y; d[2*SA_LD]=pa.z; d[3*SA_LD]=pa.w;
            sW[(bs + wK2+0)*SW_LD + wC] = pw.x;
            sW[(bs + wK2+1)*SW_LD + wC] = pw.y;
        }
        if (ch + 2 < nch) {
            pa = __ldcg((const float4*)(Ab + (size_t)aB*lA + (ch+2)*16 + aK));
            pw = __ldg((const float2*)(wrow + (ch+2)*16 + wK2));
        }
        const float* ab = sA + ((ch&1)*16)*SA_LD;
        const float* wb = sW + ((ch&1)*16)*SW_LD;
#pragma unroll
        for (int kk = 0; kk < 16; kk++) {
            float2 av = *(const float2*)(ab + kk*SA_LD + tb*2);
            const u64* wp = (const u64*)(wb + kk*SW_LD + tu*4);
            u64 wv0 = wp[0], wv1 = wp[1];
            u64 a0d = dup2(av.x), a1d = dup2(av.y);
            acc2[0][0] = ffma2(a0d, wv0, acc2[0][0]); acc2[0][1] = ffma2(a0d, wv1, acc2[0][1]);
            acc2[1][0] = ffma2(a1d, wv0, acc2[1][0]); acc2[1][1] = ffma2(a1d, wv1, acc2[1][1]);
        }
        __syncthreads();
    }
}

__global__ void __launch_bounds__(256, 1) dec_persist(
    const float* __restrict__ Wih0, const float* __restrict__ Whh0, const float* __restrict__ b0,
    const float* __restrict__ Wih1, const float* __restrict__ Whh1, const float* __restrict__ b1,
    const float* __restrict__ outW, const float* __restrict__ outb,
    float* __restrict__ out)
{
    __shared__ float sA[2*16*SA_LD];
    __shared__ float sW[2*16*SW_LD];
    __shared__ float sWc[2*16*4];

    const int blk = blockIdx.x;
    const int j0 = blk * 8;
    const int tid = threadIdx.x;
    const int tu = tid & 7;
    const int tb = tid >> 3;
    unsigned tgt = 0;

    const int aB = tid & 63, aK = (tid >> 6) * 4;
    const int wC = tid >> 3, wK2 = (tid & 7) * 2;
    const int wq = wC & 3, wu = wC >> 2;
    const int wrowi = wq*DH + j0 + wu;

    const float* wA_key = Wih0 + (size_t)wrowi * 1536 + 1024;
    const float* wA_h   = Whh0 + (size_t)wrowi * 1024;
    const float* wB_x   = Wih1 + (size_t)wrowi * 1024;
    const float* wB_h   = Whh1 + (size_t)wrowi * 1024;
    const u64 z2 = dup2(0.f);

    float c0reg[2], c1reg[2];
#pragma unroll
    for (int bb = 0; bb < 2; bb++) {
        int b = tb*2 + bb;
        int u = j0 + tu;
        float cv = (u < H) ? g_c[(size_t)1*B*H + (size_t)b*H + u]
                           : g_c[(size_t)3*B*H + (size_t)b*H + (u - H)];
        c0reg[bb] = cv; c1reg[bb] = cv;
    }
    float bia0[4], bia1[4];
    {
        int j = j0 + tu;
#pragma unroll
        for (int q = 0; q < 4; q++) { bia0[q] = __ldg(b0 + q*DH + j); bia1[q] = __ldg(b1 + q*DH + j); }
    }

    for (int t = 0; t < T; t++) {
        const float* h0prev = g_dh0 + (size_t)(t&1)*B*DH;
        float* h0n          = g_dh0 + (size_t)((t+1)&1)*B*DH;
        const float* h1prev = g_dh1 + (size_t)(t&1)*B*DH;
        float* h1n          = g_dh1 + (size_t)((t+1)&1)*B*DH;

        // ---------- phase A: layer-0 gates + cell (ctx folded into g_xc) ----------
        {
            const float* xcb = g_xc + (size_t)(t > 0 ? 64 : 0) * 4096;
            float xcv[2][4];
#pragma unroll
            for (int bb = 0; bb < 2; bb++)
#pragma unroll
                for (int q = 0; q < 4; q++)
                    xcv[bb][q] = __ldg(xcb + (size_t)(tb*2+bb)*4096 + q*DH + j0 + tu);

            u64 acc2[2][2] = {{z2,z2},{z2,z2}};
            dec_seg(g_curkey, J4, wA_key, 32, acc2, sA, sW, tb, tu, aB, aK, wC, wK2);
            dec_seg(h0prev,   DH, wA_h,   64, acc2, sA, sW, tb, tu, aB, aK, wC, wK2);

            const int j = j0 + tu;
#pragma unroll
            for (int bb = 0; bb < 2; bb++) {
                int b = tb*2 + bb;
                float2 gif = unpk(acc2[bb][0]);
                float2 ggo = unpk(acc2[bb][1]);
                float iv = sigf(gif.x + bia0[0] + xcv[bb][0]);
                float fv = sigf(gif.y + bia0[1] + xcv[bb][1]);
                float gv = tanhf(ggo.x + bia0[2] + xcv[bb][2]);
                float ov = sigf(ggo.y + bia0[3] + xcv[bb][3]);
                float cn = fv * c0reg[bb] + iv * gv;
                float hn = ov * tanhf(cn);
                c0reg[bb] = cn;
                h0n[(size_t)b*DH + j] = hn;
            }
        }
        bar_sync(&g_bar, DEC_NB, tgt);

        // ---------- phase B: layer-1 gates + cell ----------
        {
            u64 acc2[2][2] = {{z2,z2},{z2,z2}};
            dec_seg(h0n,    DH, wB_x, 64, acc2, sA, sW, tb, tu, aB, aK, wC, wK2);
            dec_seg(h1prev, DH, wB_h, 64, acc2, sA, sW, tb, tu, aB, aK, wC, wK2);

            const int j = j0 + tu;
#pragma unroll
            for (int bb = 0; bb < 2; bb++) {
                int b = tb*2 + bb;
                float2 gif = unpk(acc2[bb][0]);
                float2 ggo = unpk(acc2[bb][1]);
                float iv = sigf(gif.x + bia1[0]);
                float fv = sigf(gif.y + bia1[1]);
                float gv = tanhf(ggo.x + bia1[2]);
                float ov = sigf(ggo.y + bia1[3]);
                float cn = fv * c1reg[bb] + iv * gv;
                float hn = ov * tanhf(cn);
                c1reg[bb] = cn;
                h1n[(size_t)b*DH + j] = hn;
            }
        }
        bar_sync(&g_bar, DEC_NB, tgt);

        // ---------- phase C: out projection + next keyframe ----------
        {
            const int n0 = blk * 4;
            const int ob = tid >> 2, on = tid & 3;
            float accO = 0.f;

            float4 pa = __ldcg((const float4*)(h1n + (size_t)aB*DH + aK));
            float4 pw;
            if (tid < 16) pw = __ldg((const float4*)(outW + (size_t)(n0 + (tid&3))*DH + (tid>>2)*4));
            __syncthreads();
            {
                float* d = sA + aK*SA_LD + aB;
                d[0]=pa.x; d[SA_LD]=pa.y; d[2*SA_LD]=pa.z; d[3*SA_LD]=pa.w;
                if (tid < 16) {
                    int col = tid & 3, kq = (tid >> 2) * 4;
                    sWc[(kq+0)*4 + col] = pw.x;
                    sWc[(kq+1)*4 + col] = pw.y;
                    sWc[(kq+2)*4 + col] = pw.z;
                    sWc[(kq+3)*4 + col] = pw.w;
                }
            }
            __syncthreads();
            pa = __ldcg((const float4*)(h1n + (size_t)aB*DH + 16 + aK));
            if (tid < 16) pw = __ldg((const float4*)(outW + (size_t)(n0 + (tid&3))*DH + 16 + (tid>>2)*4));

            for (int ch = 0; ch < 64; ch++) {
                if (ch + 1 < 64) {
                    int bs = ((ch+1)&1)*16;
                    float* d = sA + (bs + aK)*SA_LD + aB;
                    d[0]=pa.x; d[SA_LD]=pa.y; d[2*SA_LD]=pa.z; d[3*SA_LD]=pa.w;
                    if (tid < 16) {
                        int col = tid & 3, kq = (tid >> 2) * 4;
                        sWc[(bs+kq+0)*4 + col] = pw.x;
                        sWc[(bs+kq+1)*4 + col] = pw.y;
                        sWc[(bs+kq+2)*4 + col] = pw.z;
                        sWc[(bs+kq+3)*4 + col] = pw.w;
                    }
                }
                if (ch + 2 < 64) {
                    pa = __ldcg((const float4*)(h1n + (size_t)aB*DH + (ch+2)*16 + aK));
                    if (tid < 16) pw = __ldg((const float4*)(outW + (size_t)(n0 + (tid&3))*DH + (ch+2)*16 + (tid>>2)*4));
                }
                const int bs = (ch&1)*16;
#pragma unroll
                for (int kk = 0; kk < 16; kk++)
                    accO += sA[(bs+kk)*SA_LD + ob] * sWc[(bs+kk)*4 + on];
                __syncthreads();
            }
            float v = accO + __ldg(outb + n0 + on);
            out[(size_t)(ob*T + t)*J4 + n0 + on] = v;
            g_curkey[ob*J4 + n0 + on] = v;
        }
        bar_sync(&g_bar, DEC_NB, tgt);
    }
}

// ---------------- launch ----------------
extern "C" void kernel_launch(void* const* d_in, const int* in_sizes, int n_in,
                              void* d_out, int out_size)
{
    const float* sa    = (const float*)d_in[0];
    const float* sb    = (const float*)d_in[1];
    const float* eWih0 = (const float*)d_in[2];
    const float* eWhh0 = (const float*)d_in[3];
    const float* eb0   = (const float*)d_in[4];
    const float* eWih1 = (const float*)d_in[5];
    const float* eWhh1 = (const float*)d_in[6];
    const float* eb1   = (const float*)d_in[7];
    const float* dWih0 = (const float*)d_in[8];
    const float* dWhh0 = (const float*)d_in[9];
    const float* db0   = (const float*)d_in[10];
    const float* dWih1 = (const float*)d_in[11];
    const float* dWhh1 = (const float*)d_in[12];
    const float* db1   = (const float*)d_in[13];
    const float* outW  = (const float*)d_in[16];
    const float* outb  = (const float*)d_in[17];
    float* out = (float*)d_out;

    float *p_xg0, *p_xg1, *p_y0, *p_y1, *p_xcin, *p_xc, *p_zero;
    cudaGetSymbolAddress((void**)&p_xg0,  g_xg0);
    cudaGetSymbolAddress((void**)&p_xg1,  g_xg1);
    cudaGetSymbolAddress((void**)&p_y0,   g_y0);
    cudaGetSymbolAddress((void**)&p_y1,   g_y1);
    cudaGetSymbolAddress((void**)&p_xcin, g_xcin);
    cudaGetSymbolAddress((void**)&p_xc,   g_xc);
    cudaGetSymbolAddress((void**)&p_zero, g_zero);

    cudaFuncSetAttribute(enc_persist, cudaFuncAttributeMaxDynamicSharedMemorySize, ENC_SMEM);

    dim3 gemm_grid(H4 / 128, (B * S) / 128);

    for (int inp = 0; inp < 2; inp++)
        for (int dir = 0; dir < 2; dir++)
            sgemm_bias<<<gemm_grid, 256>>>(
                inp ? sb : sa,
                eWih0 + (size_t)dir * H4 * E,
                eb0 + (size_t)dir * H4,
                p_xg0 + (size_t)(inp * 2 + dir) * B * S * H4,
                B * S, H4, E, E, E);

    reset_bar<<<1, 32>>>();
    enc_persist<<<ENC_NB, 256, ENC_SMEM>>>(p_xg0, eWhh0, p_y0, 0);

    for (int inp = 0; inp < 2; inp++)
        for (int dir = 0; dir < 2; dir++)
            sgemm_bias<<<gemm_grid, 256>>>(
                p_y0 + (size_t)inp * B * S * H2,
                eWih1 + (size_t)dir * H4 * H2,
                eb1 + (size_t)dir * H4,
                p_xg1 + (size_t)(inp * 2 + dir) * B * S * H4,
                B * S, H4, H2, H2, H2);

    reset_bar<<<1, 32>>>();
    enc_persist<<<ENC_NB, 256, ENC_SMEM>>>(p_xg1, eWhh1, p_y1, 1);

    dec_setup<<<(B * DH + 255) / 256, 256>>>();   // resets g_bar, fills g_xcin

    // xc = [x0ctx; ctx] @ dec_Wih0[:, :1024]^T  (M=128, N=4096, K=1024)
    sgemm_bias<<<dim3(4096/128, 1), 256>>>(p_xcin, dWih0, p_zero, p_xc,
                                           128, 4096, 1024, 1024, 1536);

    dec_persist<<<DEC_NB, 256>>>(dWih0, dWhh0, db0, dWih1, dWhh1, db1, outW, outb, out);
}